// round 12
// baseline (speedup 1.0000x reference)
#include <cuda_runtime.h>
#include <cuda_bf16.h>
#include <math.h>
#include <stdint.h>

#define Bz 64
#define Tz 512
#define Dz 1024
#define Hz 1024
#define Gz 4096          // 4*H
#define EPSz 1e-5f
#define NCTA 128

typedef unsigned long long ull;

// ---------------- scratch (device globals; no runtime allocation) ----------------
__device__ float g_gih[(size_t)2 * Tz * Bz * Gz];      // LN'd input gates [dir][t][b][4H]
__device__ __align__(16) unsigned g_wfh[(size_t)2 * 256 * 64 * 128];
__device__ __align__(16) unsigned g_wfl[(size_t)2 * 256 * 64 * 128];
__device__ __align__(16) unsigned g_wihfh[(size_t)2 * 256 * 64 * 128];
__device__ __align__(16) unsigned g_wihfl[(size_t)2 * 256 * 64 * 128];
__device__ __align__(16) unsigned g_xfh[(size_t)512 * 64 * 4 * 128];
__device__ __align__(16) unsigned g_xfl[(size_t)512 * 64 * 4 * 128];
__device__ __align__(16) unsigned g_hfh[2 * 64 * 4 * 128];
__device__ __align__(16) unsigned g_hfl[2 * 64 * 4 * 128];
__device__ float g_part[8 * Bz * Gz];                  // [ks 0..3][dir][b][4H]
__device__ float g_c[2 * Bz * Hz];                     // cell state
// flag barrier state: per-CTA flags at 128B stride, per-dir release word
__device__ unsigned g_flags[2][64 * 32];
__device__ unsigned g_rel[2 * 32];

// ---------------- helpers ----------------
__device__ __forceinline__ void split_bf16(float v, __nv_bfloat16& hi, __nv_bfloat16& lo) {
    hi = __float2bfloat16(v);
    lo = __float2bfloat16(v - __bfloat162float(hi));
}
__device__ __forceinline__ unsigned pack2(__nv_bfloat16 a, __nv_bfloat16 b) {
    return (unsigned)__bfloat16_as_ushort(a) | ((unsigned)__bfloat16_as_ushort(b) << 16);
}
__device__ __forceinline__ float tanh_ap(float x) {
    float y;
    asm("tanh.approx.f32 %0, %1;" : "=f"(y) : "f"(x));
    return y;
}
__device__ __forceinline__ float sig_ap(float x) {
    return 0.5f * tanh_ap(0.5f * x) + 0.5f;
}

// HMMA m16n8k16 bf16 row.col, f32 accumulate
__device__ __forceinline__ void mma16816(float* c, const uint4& a, unsigned b0, unsigned b1) {
    asm volatile(
        "mma.sync.aligned.m16n8k16.row.col.f32.bf16.bf16.f32 "
        "{%0,%1,%2,%3}, {%4,%5,%6,%7}, {%8,%9}, {%0,%1,%2,%3};"
        : "+f"(c[0]), "+f"(c[1]), "+f"(c[2]), "+f"(c[3])
        : "r"(a.x), "r"(a.y), "r"(a.z), "r"(a.w), "r"(b0), "r"(b1));
}

// per-dir flag barrier: 64 CTAs, no atomic contention, monotonic generations.
// dgrp = dir group (0/1), sub = CTA index within group (0..63), master = sub 0.
__device__ __forceinline__ void gbar_dir(int dgrp, int sub, unsigned gen, int tid) {
    __syncthreads();
    if (tid == 0) {
        __threadfence();
        *(volatile unsigned*)&g_flags[dgrp][sub * 32] = gen;
    }
    if (sub == 0) {
        if (tid < 64) {
            while (*(volatile unsigned*)&g_flags[dgrp][tid * 32] < gen) { }
        }
        __syncthreads();   // all master threads: every flag observed
        if (tid == 0) {
            __threadfence();
            *(volatile unsigned*)&g_rel[dgrp * 32] = gen;
        }
    } else {
        if (tid == 0) {
            while (*(volatile unsigned*)&g_rel[dgrp * 32] < gen) { }
            __threadfence();
        }
        __syncthreads();
    }
}

// ---------------- prep: weight [4096][1024] -> bf16 hi/lo B-fragment images ----------------
__global__ void prep_wfrag_kernel(const float* __restrict__ w_f, const float* __restrict__ w_b,
                                  int sel) {
    unsigned* __restrict__ outh = sel ? g_wihfh : g_wfh;
    unsigned* __restrict__ outl = sel ? g_wihfl : g_wfl;
    int gid = blockIdx.x * 256 + threadIdx.x;
    int T     = gid & 31;
    int kstep = (gid >> 5) & 63;
    int wn    = (gid >> 11) & 255;
    int dir   = gid >> 19;
    const float* __restrict__ W = dir ? w_b : w_f;
    unsigned hw[4], lw[4];
#pragma unroll
    for (int q = 0; q < 4; q++) {
        int c = wn * 16 + (q >> 1) * 8 + (T >> 2);
        int k = kstep * 16 + ((q & 1) * 4 + (T & 3)) * 2;
        float2 v = *(const float2*)(W + (size_t)c * Hz + k);
        __nv_bfloat16 h0, l0, h1, l1;
        split_bf16(v.x, h0, l0);
        split_bf16(v.y, h1, l1);
        hw[q] = pack2(h0, h1);
        lw[q] = pack2(l0, l1);
    }
    size_t base = ((size_t)(dir * 256 + wn) * 64 + kstep) * 128 + T * 4;
    *(uint4*)&outh[base] = make_uint4(hw[0], hw[1], hw[2], hw[3]);
    *(uint4*)&outl[base] = make_uint4(lw[0], lw[1], lw[2], lw[3]);
}

// ---------------- prep: x -> bf16 hi/lo A-fragment images ----------------
__global__ void prep_x_kernel(const float* __restrict__ x) {
    int gid = blockIdx.x * 256 + threadIdx.x;
    int kw = gid & 511;
    int b  = (gid >> 9) & 63;
    int t  = gid >> 15;
    float2 v = *(const float2*)(x + ((size_t)b * Tz + t) * Dz + kw * 2);
    __nv_bfloat16 h0, l0, h1, l1;
    split_bf16(v.x, h0, l0);
    split_bf16(v.y, h1, l1);
    int kstep = kw >> 3;
    int pk = kw & 7;
    int r16 = b & 15;
    int mt = b >> 4;
    int T = (r16 & 7) * 4 + (pk & 3);
    int q = (pk >= 4 ? 2 : 0) + (r16 >= 8 ? 1 : 0);
    size_t widx = ((size_t)(t * 64 + kstep) * 4 + mt) * 128 + T * 4 + q;
    g_xfh[widx] = pack2(h0, h1);
    g_xfl[widx] = pack2(l0, l1);
}

// ---------------- input-side GEMM: HMMA bf16-split ----------------
__global__ __launch_bounds__(256)
void gemm_ih_hmma(const float* __restrict__ bias_f, const float* __restrict__ bias_b) {
    __shared__ uint4 As[2][512];
    __shared__ uint4 Al[2][512];
    const int tid = threadIdx.x;
    const int lane = tid & 31;
    const int wrp = tid >> 5;
    const int dir = blockIdx.x >> 5;
    const int ntile = blockIdx.x & 31;
    const int mtile = blockIdx.y;
    const int wm = wrp >> 2;
    const int wn4 = wrp & 3;
    const float* __restrict__ bias = dir ? bias_b : bias_f;

    const int wn0 = ntile * 8 + wn4 * 2;
    const uint4* pb0h = (const uint4*)g_wihfh + ((size_t)(dir * 256 + wn0) * 64) * 32 + lane;
    const uint4* pb0l = (const uint4*)g_wihfl + ((size_t)(dir * 256 + wn0) * 64) * 32 + lane;
    const uint4* pb1h = (const uint4*)g_wihfh + ((size_t)(dir * 256 + wn0 + 1) * 64) * 32 + lane;
    const uint4* pb1l = (const uint4*)g_wihfl + ((size_t)(dir * 256 + wn0 + 1) * 64) * 32 + lane;

    const uint4* gxh = (const uint4*)g_xfh;
    const uint4* gxl = (const uint4*)g_xfl;

    auto gaddrA = [&](int c, int u) -> size_t {
        int block = u >> 5;
        int ks2 = block >> 3;
        int mtg = block & 7;
        int l4 = u & 31;
        int v = mtile * 2 + (mtg >> 2);
        int t = dir ? (511 - v) : v;
        return ((size_t)(t * 64 + c * 2 + ks2) * 4 + (mtg & 3)) * 32 + l4;
    };

    float acc[4][4][4];
#pragma unroll
    for (int i = 0; i < 4; i++)
#pragma unroll
        for (int n = 0; n < 4; n++)
#pragma unroll
            for (int j = 0; j < 4; j++) acc[i][n][j] = 0.f;

    As[0][tid] = gxh[gaddrA(0, tid)];
    As[0][tid + 256] = gxh[gaddrA(0, tid + 256)];
    Al[0][tid] = gxl[gaddrA(0, tid)];
    Al[0][tid + 256] = gxl[gaddrA(0, tid + 256)];
    __syncthreads();

    uint4 cb0h = pb0h[0], cb0l = pb0l[0], cb1h = pb1h[0], cb1l = pb1l[0];

    for (int c = 0; c < 32; c++) {
        const int cur = c & 1;
        uint4 rh0, rh1, rl0, rl1;
        if (c < 31) {
            rh0 = gxh[gaddrA(c + 1, tid)];
            rh1 = gxh[gaddrA(c + 1, tid + 256)];
            rl0 = gxl[gaddrA(c + 1, tid)];
            rl1 = gxl[gaddrA(c + 1, tid + 256)];
        }
#pragma unroll
        for (int ks2 = 0; ks2 < 2; ks2++) {
            const int kstep = c * 2 + ks2;
            uint4 nb0h = cb0h, nb0l = cb0l, nb1h = cb1h, nb1l = cb1l;
            if (kstep < 63) {
                size_t o = (size_t)(kstep + 1) * 32;
                nb0h = pb0h[o]; nb0l = pb0l[o];
                nb1h = pb1h[o]; nb1l = pb1l[o];
            }
            uint4 ah[4], al[4];
#pragma unroll
            for (int i = 0; i < 4; i++) {
                int sb = (ks2 * 8 + wm * 4 + i) * 32 + lane;
                ah[i] = As[cur][sb];
                al[i] = Al[cur][sb];
            }
#pragma unroll
            for (int i = 0; i < 4; i++) {
                mma16816(acc[i][0], ah[i], cb0h.x, cb0h.y);
                mma16816(acc[i][0], al[i], cb0h.x, cb0h.y);
                mma16816(acc[i][0], ah[i], cb0l.x, cb0l.y);
                mma16816(acc[i][1], ah[i], cb0h.z, cb0h.w);
                mma16816(acc[i][1], al[i], cb0h.z, cb0h.w);
                mma16816(acc[i][1], ah[i], cb0l.z, cb0l.w);
                mma16816(acc[i][2], ah[i], cb1h.x, cb1h.y);
                mma16816(acc[i][2], al[i], cb1h.x, cb1h.y);
                mma16816(acc[i][2], ah[i], cb1l.x, cb1l.y);
                mma16816(acc[i][3], ah[i], cb1h.z, cb1h.w);
                mma16816(acc[i][3], al[i], cb1h.z, cb1h.w);
                mma16816(acc[i][3], ah[i], cb1l.z, cb1l.w);
            }
            cb0h = nb0h; cb0l = nb0l; cb1h = nb1h; cb1l = nb1l;
        }
        if (c < 31) {
            const int nxt = cur ^ 1;
            As[nxt][tid] = rh0; As[nxt][tid + 256] = rh1;
            Al[nxt][tid] = rl0; Al[nxt][tid + 256] = rl1;
            __syncthreads();
        }
    }

    const int r0 = lane >> 2;
    const int cp = (lane & 3) * 2;
    float* outbase = g_gih + (size_t)dir * (Tz * Bz) * Gz;
#pragma unroll
    for (int i = 0; i < 4; i++) {
        const int mtg = wm * 4 + i;
        const int rbase = mtile * 128 + (mtg >> 2) * 64 + (mtg & 3) * 16;
#pragma unroll
        for (int n8 = 0; n8 < 4; n8++) {
            const int col = ntile * 128 + wn4 * 32 + n8 * 8 + cp;
            float2 bv = *(const float2*)(bias + col);
            float* d0 = outbase + (size_t)(rbase + r0) * Gz + col;
            float* d1 = outbase + (size_t)(rbase + r0 + 8) * Gz + col;
            *(float2*)d0 = make_float2(acc[i][n8][0] + bv.x, acc[i][n8][1] + bv.y);
            *(float2*)d1 = make_float2(acc[i][n8][2] + bv.x, acc[i][n8][3] + bv.y);
        }
    }
}

// ---------------- LayerNorm over 4096 (in place) ----------------
__global__ void ln_ih_kernel(const float* __restrict__ gain_f, const float* __restrict__ beta_f,
                             const float* __restrict__ gain_b, const float* __restrict__ beta_b) {
    const int row = blockIdx.x;
    const int dir = row >> 15;
    const float* __restrict__ gain = dir ? gain_b : gain_f;
    const float* __restrict__ beta = dir ? beta_b : beta_f;
    float* p = g_gih + (size_t)row * Gz;
    const int tid = threadIdx.x;

    float4 v[4];
    float sum = 0.f, sq = 0.f;
#pragma unroll
    for (int g = 0; g < 4; g++) {
        v[g] = *(const float4*)(p + g * 1024 + tid * 4);
        sum += v[g].x + v[g].y + v[g].z + v[g].w;
        sq  += v[g].x * v[g].x + v[g].y * v[g].y + v[g].z * v[g].z + v[g].w * v[g].w;
    }
    __shared__ float red[512];
    red[tid] = sum; red[256 + tid] = sq;
    __syncthreads();
    for (int s = 128; s > 0; s >>= 1) {
        if (tid < s) { red[tid] += red[tid + s]; red[256 + tid] += red[256 + tid + s]; }
        __syncthreads();
    }
    float mu = red[0] * (1.f / Gz);
    float var = red[256] * (1.f / Gz) - mu * mu;
    float sc = rsqrtf(var + EPSz);
#pragma unroll
    for (int g = 0; g < 4; g++) {
        int c = g * 1024 + tid * 4;
        float4 gv = *(const float4*)(gain + c);
        float4 bvv = *(const float4*)(beta + c);
        float4 o;
        o.x = (v[g].x - mu) * sc * gv.x + bvv.x;
        o.y = (v[g].y - mu) * sc * gv.y + bvv.y;
        o.z = (v[g].z - mu) * sc * gv.z + bvv.z;
        o.w = (v[g].w - mu) * sc * gv.w + bvv.w;
        *(float4*)(p + c) = o;
    }
}

// h A-fragment write: element (b=row, k) of dir -> word index
__device__ __forceinline__ void hfrag_addr(int dir, int b, int k, size_t& widx) {
    int kstep = k >> 4;
    int pk = (k >> 1) & 7;
    int r16 = b & 15;
    int mt = b >> 4;
    int T = (r16 & 7) * 4 + (pk & 3);
    int q = (pk >= 4 ? 2 : 0) + (r16 >= 8 ? 1 : 0);
    widx = ((size_t)(dir * 64 + kstep) * 4 + mt) * 128 + T * 4 + q;
}

// ---------------- persistent recurrence: W-hi in SMEM, flag barriers per dir ----------------
#define SMEM_BYTES (131072 + 256)

__global__ __launch_bounds__(512, 1)
void lstm_persistent(const float* __restrict__ bhh_f, const float* __restrict__ ghh_f,
                     const float* __restrict__ behh_f,
                     const float* __restrict__ bhh_b, const float* __restrict__ ghh_b,
                     const float* __restrict__ behh_b,
                     const float* __restrict__ fwd_init, const float* __restrict__ bwd_init,
                     float* __restrict__ out) {
    extern __shared__ __align__(16) char smem[];
    uint4* ws = (uint4*)smem;                       // [16 wn][16 kstep][32 uint4] W-hi
    float* red = (float*)(smem + 131072);           // [64]

    const int tid = threadIdx.x;
    const int bid = blockIdx.x;
    const int wrp = tid >> 5;
    const int lane = tid & 31;
    const int dgrp = bid >> 6;                      // barrier group = dir
    const int sub  = bid & 63;

    // ---- init h0/c0 (per-dir partition: 64 CTAs x 512 thr cover Bz*Hz with 2 elems/thr) ----
    for (int e = sub * 512 + tid; e < Bz * Hz; e += 64 * 512) {
        int b = e >> 10;
        int k = e & 1023;
        const float* init = dgrp ? bwd_init : fwd_init;
        float hv = init[k];
        g_c[(size_t)(dgrp * Bz + b) * Hz + k] = init[Hz + k];
        __nv_bfloat16 hh, hl;
        split_bf16(hv, hh, hl);
        size_t widx;
        hfrag_addr(dgrp, b, k, widx);
        int half = k & 1;
        ((__nv_bfloat16*)&g_hfh[widx])[half] = hh;
        ((__nv_bfloat16*)&g_hfl[widx])[half] = hl;
    }

    // ---- phase A identifiers: bid = dir*64 + nt*4 + ks ----
    const int dirA = dgrp;
    const int nt   = sub >> 2;
    const int ks   = sub & 3;
    const int wn   = nt * 16 + wrp;
    const uint4* pbl = (const uint4*)g_wfl + ((size_t)(dirA * 256 + wn) * 64 + ks * 16) * 32 + lane;
    const uint4* pah = (const uint4*)g_hfh + (size_t)(dirA * 64 + ks * 16) * 128 + lane;
    const uint4* pal = (const uint4*)g_hfl + (size_t)(dirA * 64 + ks * 16) * 128 + lane;

    // ---- load per-CTA W-hi slice into SMEM (once) ----
    {
        const uint4* src = (const uint4*)g_wfh
            + ((size_t)(dirA * 256 + nt * 16) * 64 + ks * 16) * 32;
#pragma unroll
        for (int j = 0; j < 16; j++) {
            int u = tid + j * 512;
            int w = u >> 9;
            int rem = u & 511;
            ws[u] = src[(size_t)w * (64 * 32) + rem];
        }
    }

    // ---- phase B identifiers ----
    const int dirB = dgrp;
    const int cb   = sub;
    const float* __restrict__ bhh  = dirB ? bhh_b  : bhh_f;
    const float* __restrict__ ghh  = dirB ? ghh_b  : ghh_f;
    const float* __restrict__ behh = dirB ? behh_b : behh_f;
    float* cptr = g_c + ((size_t)dirB * Bz + cb) * Hz + tid * 2;
    float* o2   = out + (size_t)Bz * Tz * 2 * Hz + (size_t)cb * (2 * Hz) + dirB * Hz + tid * 2;
    const int kstepB = tid >> 3;
    const int pkB = tid & 7;
    const int r16B = cb & 15;
    const int mtB = cb >> 4;
    const size_t hwordB = ((size_t)(dirB * 64 + kstepB) * 4 + mtB) * 128
                          + ((r16B & 7) * 4 + (pkB & 3)) * 4
                          + (pkB >= 4 ? 2 : 0) + (r16B >= 8 ? 1 : 0);

    unsigned gen = 0;
    gen++; gbar_dir(dgrp, sub, gen, tid);   // init + SMEM W loaded

    for (int t = 0; t < Tz; t++) {
        // ---- prefetch this step's gih slice ----
        float2 gi[4];
        {
            const float* gih = g_gih + ((size_t)dirB * Tz * Bz + (size_t)t * Bz + cb) * Gz;
#pragma unroll
            for (int g = 0; g < 4; g++)
                gi[g] = *(const float2*)(gih + g * 1024 + tid * 2);
        }

        // ================= phase A: HMMA GEMM (16 ksteps) =================
        float acc[4][2][4];
#pragma unroll
        for (int m = 0; m < 4; m++)
#pragma unroll
            for (int n = 0; n < 2; n++)
#pragma unroll
                for (int j = 0; j < 4; j++) acc[m][n][j] = 0.f;

        uint4 cbl = pbl[0];
#pragma unroll 4
        for (int kk = 0; kk < 16; kk++) {
            const uint4* ah4 = pah + (size_t)kk * 128;
            const uint4* al4 = pal + (size_t)kk * 128;
            uint4 ah0 = ah4[0],  ah1 = ah4[32],  ah2 = ah4[64],  ah3 = ah4[96];
            uint4 al0 = al4[0],  al1 = al4[32],  al2 = al4[64],  al3 = al4[96];
            uint4 cbh = ws[(wrp * 16 + kk) * 32 + lane];
            uint4 nbl = cbl;
            if (kk < 15) nbl = pbl[(size_t)(kk + 1) * 32];
            mma16816(acc[0][0], ah0, cbh.x, cbh.y);
            mma16816(acc[0][0], al0, cbh.x, cbh.y);
            mma16816(acc[0][0], ah0, cbl.x, cbl.y);
            mma16816(acc[0][1], ah0, cbh.z, cbh.w);
            mma16816(acc[0][1], al0, cbh.z, cbh.w);
            mma16816(acc[0][1], ah0, cbl.z, cbl.w);
            mma16816(acc[1][0], ah1, cbh.x, cbh.y);
            mma16816(acc[1][0], al1, cbh.x, cbh.y);
            mma16816(acc[1][0], ah1, cbl.x, cbl.y);
            mma16816(acc[1][1], ah1, cbh.z, cbh.w);
            mma16816(acc[1][1], al1, cbh.z, cbh.w);
            mma16816(acc[1][1], ah1, cbl.z, cbl.w);
            mma16816(acc[2][0], ah2, cbh.x, cbh.y);
            mma16816(acc[2][0], al2, cbh.x, cbh.y);
            mma16816(acc[2][0], ah2, cbl.x, cbl.y);
            mma16816(acc[2][1], ah2, cbh.z, cbh.w);
            mma16816(acc[2][1], al2, cbh.z, cbh.w);
            mma16816(acc[2][1], ah2, cbl.z, cbl.w);
            mma16816(acc[3][0], ah3, cbh.x, cbh.y);
            mma16816(acc[3][0], al3, cbh.x, cbh.y);
            mma16816(acc[3][0], ah3, cbl.x, cbl.y);
            mma16816(acc[3][1], ah3, cbh.z, cbh.w);
            mma16816(acc[3][1], al3, cbh.z, cbh.w);
            mma16816(acc[3][1], ah3, cbl.z, cbl.w);
            cbl = nbl;
        }

        // epilogue: write C fragments to g_part [ks][dir][b][col]
        {
            const int r0 = lane >> 2;
            const int cc = wn * 16 + (lane & 3) * 2;
            float* pb = g_part + (size_t)(ks * 2 + dirA) * Bz * Gz;
#pragma unroll
            for (int m = 0; m < 4; m++) {
#pragma unroll
                for (int n = 0; n < 2; n++) {
                    int col = cc + n * 8;
                    *(float2*)&pb[(size_t)(m * 16 + r0) * Gz + col] =
                        make_float2(acc[m][n][0], acc[m][n][1]);
                    *(float2*)&pb[(size_t)(m * 16 + r0 + 8) * Gz + col] =
                        make_float2(acc[m][n][2], acc[m][n][3]);
                }
            }
        }

        gen++; gbar_dir(dgrp, sub, gen, tid);   // all partial tiles visible

        // ================= phase B: sum 4 partials + LN + cell =================
        {
            float2 raw[4];
            float sum = 0.f, sq = 0.f;
#pragma unroll
            for (int g = 0; g < 4; g++) {
                int c = g * 1024 + tid * 2;
                const float* pbase = g_part + ((size_t)dirB * Bz + cb) * Gz + c;
                float2 p0 = *(const float2*)(pbase + (size_t)0 * 2 * Bz * Gz);
                float2 p1 = *(const float2*)(pbase + (size_t)1 * 2 * Bz * Gz);
                float2 p2 = *(const float2*)(pbase + (size_t)2 * 2 * Bz * Gz);
                float2 p3 = *(const float2*)(pbase + (size_t)3 * 2 * Bz * Gz);
                float2 bh = *(const float2*)(bhh + c);
                float2 r;
                r.x = p0.x + p1.x + p2.x + p3.x + bh.x;
                r.y = p0.y + p1.y + p2.y + p3.y + bh.y;
                raw[g] = r;
                sum += r.x + r.y;
                sq  += r.x * r.x + r.y * r.y;
            }
#pragma unroll
            for (int off = 16; off; off >>= 1) {
                sum += __shfl_xor_sync(0xffffffffu, sum, off);
                sq  += __shfl_xor_sync(0xffffffffu, sq, off);
            }
            if (lane == 0) { red[wrp] = sum; red[32 + wrp] = sq; }
            __syncthreads();
            float ts = 0.f, tq = 0.f;
#pragma unroll
            for (int i = 0; i < 16; i++) { ts += red[i]; tq += red[32 + i]; }
            float mu = ts * (1.f / Gz);
            float var = tq * (1.f / Gz) - mu * mu;
            float sc = rsqrtf(var + EPSz);

            float gate[4][2];
#pragma unroll
            for (int g = 0; g < 4; g++) {
                int c = g * 1024 + tid * 2;
                float2 gg = *(const float2*)(ghh + c);
                float2 be = *(const float2*)(behh + c);
                gate[g][0] = gi[g].x + (raw[g].x - mu) * sc * gg.x + be.x;
                gate[g][1] = gi[g].y + (raw[g].y - mu) * sc * gg.y + be.y;
            }
            float* optr = out + ((size_t)cb * Tz + t) * (2 * Hz) + dirB * Hz + tid * 2;
            float hn2[2];
#pragma unroll
            for (int q = 0; q < 2; q++) {
                float iv = sig_ap(gate[0][q]);
                float fv = sig_ap(gate[1][q]);
                float gv = tanh_ap(gate[2][q]);
                float ov = sig_ap(gate[3][q]);
                float cn = fv * cptr[q] + iv * gv;
                float hn = ov * tanh_ap(cn);
                cptr[q] = cn;
                hn2[q] = hn;
                optr[q] = hn;
                if (t == Tz - 1) o2[q] = hn;
            }
            __nv_bfloat16 h0, l0, h1, l1;
            split_bf16(hn2[0], h0, l0);
            split_bf16(hn2[1], h1, l1);
            g_hfh[hwordB] = pack2(h0, h1);
            g_hfl[hwordB] = pack2(l0, l1);
        }

        gen++; gbar_dir(dgrp, sub, gen, tid);   // new h visible
    }
}

// ---------------- launch ----------------
extern "C" void kernel_launch(void* const* d_in, const int* in_sizes, int n_in,
                              void* d_out, int out_size) {
    const float* x      = (const float*)d_in[0];
    const float* wih_f  = (const float*)d_in[1];
    const float* whh_f  = (const float*)d_in[2];
    const float* bih_f  = (const float*)d_in[3];
    const float* bhh_f  = (const float*)d_in[4];
    const float* gih_f  = (const float*)d_in[5];
    const float* beih_f = (const float*)d_in[6];
    const float* ghh_f  = (const float*)d_in[7];
    const float* behh_f = (const float*)d_in[8];
    const float* wih_b  = (const float*)d_in[9];
    const float* whh_b  = (const float*)d_in[10];
    const float* bih_b  = (const float*)d_in[11];
    const float* bhh_b  = (const float*)d_in[12];
    const float* gih_b  = (const float*)d_in[13];
    const float* beih_b = (const float*)d_in[14];
    const float* ghh_b  = (const float*)d_in[15];
    const float* behh_b = (const float*)d_in[16];
    const float* fwd_init = (const float*)d_in[17];
    const float* bwd_init = (const float*)d_in[18];
    float* out = (float*)d_out;

    static int smem_set = 0;
    if (!smem_set) {
        cudaFuncSetAttribute(lstm_persistent,
                             cudaFuncAttributeMaxDynamicSharedMemorySize, SMEM_BYTES);
        smem_set = 1;
    }

    prep_wfrag_kernel<<<4096, 256>>>(whh_f, whh_b, 0);
    prep_wfrag_kernel<<<4096, 256>>>(wih_f, wih_b, 1);
    prep_x_kernel<<<65536, 256>>>(x);
    gemm_ih_hmma<<<dim3(64, 256), 256>>>(bih_f, bih_b);
    ln_ih_kernel<<<65536, 256>>>(gih_f, beih_f, gih_b, beih_b);
    lstm_persistent<<<NCTA, 512, SMEM_BYTES>>>(bhh_f, ghh_f, behh_f,
                                               bhh_b, ghh_b, behh_b,
                                               fwd_init, bwd_init, out);
}

// round 13
// speedup vs baseline: 1.0831x; 1.0831x over previous
#include <cuda_runtime.h>
#include <cuda_bf16.h>
#include <math.h>
#include <stdint.h>

#define Bz 64
#define Tz 512
#define Dz 1024
#define Hz 1024
#define Gz 4096          // 4*H
#define EPSz 1e-5f
#define NCTA 128

typedef unsigned long long ull;

// ---------------- scratch (device globals; no runtime allocation) ----------------
__device__ float g_gih[(size_t)2 * Tz * Bz * Gz];      // RAW input gates + bias [dir][t][b][4H]
__device__ float g_lnst[(size_t)2 * Tz * Bz * 2];      // per-row LN stats: mu, rsigma
__device__ __align__(16) unsigned g_wfh[(size_t)2 * 256 * 64 * 128];
__device__ __align__(16) unsigned g_wfl[(size_t)2 * 256 * 64 * 128];
__device__ __align__(16) unsigned g_wihfh[(size_t)2 * 256 * 64 * 128];
__device__ __align__(16) unsigned g_wihfl[(size_t)2 * 256 * 64 * 128];
__device__ __align__(16) unsigned g_xfh[(size_t)512 * 64 * 4 * 128];
__device__ __align__(16) unsigned g_xfl[(size_t)512 * 64 * 4 * 128];
__device__ __align__(16) unsigned g_hfh[2 * 64 * 4 * 128];
__device__ __align__(16) unsigned g_hfl[2 * 64 * 4 * 128];
__device__ float g_part[8 * Bz * Gz];                  // [ks 0..3][dir][b][4H]
__device__ float g_c[2 * Bz * Hz];                     // cell state
__device__ unsigned g_cnt = 0;
__device__ unsigned g_gen = 0;

// ---------------- helpers ----------------
__device__ __forceinline__ void split_bf16(float v, __nv_bfloat16& hi, __nv_bfloat16& lo) {
    hi = __float2bfloat16(v);
    lo = __float2bfloat16(v - __bfloat162float(hi));
}
__device__ __forceinline__ unsigned pack2(__nv_bfloat16 a, __nv_bfloat16 b) {
    return (unsigned)__bfloat16_as_ushort(a) | ((unsigned)__bfloat16_as_ushort(b) << 16);
}
__device__ __forceinline__ float tanh_ap(float x) {
    float y;
    asm("tanh.approx.f32 %0, %1;" : "=f"(y) : "f"(x));
    return y;
}
__device__ __forceinline__ float sig_ap(float x) {
    return 0.5f * tanh_ap(0.5f * x) + 0.5f;
}

// HMMA m16n8k16 bf16 row.col, f32 accumulate
__device__ __forceinline__ void mma16816(float* c, const uint4& a, unsigned b0, unsigned b1) {
    asm volatile(
        "mma.sync.aligned.m16n8k16.row.col.f32.bf16.bf16.f32 "
        "{%0,%1,%2,%3}, {%4,%5,%6,%7}, {%8,%9}, {%0,%1,%2,%3};"
        : "+f"(c[0]), "+f"(c[1]), "+f"(c[2]), "+f"(c[3])
        : "r"(a.x), "r"(a.y), "r"(a.z), "r"(a.w), "r"(b0), "r"(b1));
}

// grid-wide barrier (sense-reversing), all NCTA CTAs co-resident  [R10 version]
__device__ __forceinline__ void gbar() {
    __syncthreads();
    if (threadIdx.x == 0) {
        unsigned gen = *(volatile unsigned*)&g_gen;
        __threadfence();
        unsigned old = atomicAdd(&g_cnt, 1u);
        if (old == NCTA - 1) {
            atomicExch(&g_cnt, 0u);
            __threadfence();
            atomicAdd(&g_gen, 1u);
        } else {
            while (*(volatile unsigned*)&g_gen == gen) __nanosleep(32);
        }
        __threadfence();
    }
    __syncthreads();
}

// ---------------- prep: weight [4096][1024] -> bf16 hi/lo B-fragment images ----------------
__global__ void prep_wfrag_kernel(const float* __restrict__ w_f, const float* __restrict__ w_b,
                                  int sel) {
    unsigned* __restrict__ outh = sel ? g_wihfh : g_wfh;
    unsigned* __restrict__ outl = sel ? g_wihfl : g_wfl;
    int gid = blockIdx.x * 256 + threadIdx.x;
    int T     = gid & 31;
    int kstep = (gid >> 5) & 63;
    int wn    = (gid >> 11) & 255;
    int dir   = gid >> 19;
    const float* __restrict__ W = dir ? w_b : w_f;
    unsigned hw[4], lw[4];
#pragma unroll
    for (int q = 0; q < 4; q++) {
        int c = wn * 16 + (q >> 1) * 8 + (T >> 2);
        int k = kstep * 16 + ((q & 1) * 4 + (T & 3)) * 2;
        float2 v = *(const float2*)(W + (size_t)c * Hz + k);
        __nv_bfloat16 h0, l0, h1, l1;
        split_bf16(v.x, h0, l0);
        split_bf16(v.y, h1, l1);
        hw[q] = pack2(h0, h1);
        lw[q] = pack2(l0, l1);
    }
    size_t base = ((size_t)(dir * 256 + wn) * 64 + kstep) * 128 + T * 4;
    *(uint4*)&outh[base] = make_uint4(hw[0], hw[1], hw[2], hw[3]);
    *(uint4*)&outl[base] = make_uint4(lw[0], lw[1], lw[2], lw[3]);
}

// ---------------- prep: x -> bf16 hi/lo A-fragment images ----------------
__global__ void prep_x_kernel(const float* __restrict__ x) {
    int gid = blockIdx.x * 256 + threadIdx.x;
    int kw = gid & 511;
    int b  = (gid >> 9) & 63;
    int t  = gid >> 15;
    float2 v = *(const float2*)(x + ((size_t)b * Tz + t) * Dz + kw * 2);
    __nv_bfloat16 h0, l0, h1, l1;
    split_bf16(v.x, h0, l0);
    split_bf16(v.y, h1, l1);
    int kstep = kw >> 3;
    int pk = kw & 7;
    int r16 = b & 15;
    int mt = b >> 4;
    int T = (r16 & 7) * 4 + (pk & 3);
    int q = (pk >= 4 ? 2 : 0) + (r16 >= 8 ? 1 : 0);
    size_t widx = ((size_t)(t * 64 + kstep) * 4 + mt) * 128 + T * 4 + q;
    g_xfh[widx] = pack2(h0, h1);
    g_xfl[widx] = pack2(l0, l1);
}

// ---------------- input-side GEMM: HMMA bf16-split (unchanged) ----------------
__global__ __launch_bounds__(256)
void gemm_ih_hmma(const float* __restrict__ bias_f, const float* __restrict__ bias_b) {
    __shared__ uint4 As[2][512];
    __shared__ uint4 Al[2][512];
    const int tid = threadIdx.x;
    const int lane = tid & 31;
    const int wrp = tid >> 5;
    const int dir = blockIdx.x >> 5;
    const int ntile = blockIdx.x & 31;
    const int mtile = blockIdx.y;
    const int wm = wrp >> 2;
    const int wn4 = wrp & 3;
    const float* __restrict__ bias = dir ? bias_b : bias_f;

    const int wn0 = ntile * 8 + wn4 * 2;
    const uint4* pb0h = (const uint4*)g_wihfh + ((size_t)(dir * 256 + wn0) * 64) * 32 + lane;
    const uint4* pb0l = (const uint4*)g_wihfl + ((size_t)(dir * 256 + wn0) * 64) * 32 + lane;
    const uint4* pb1h = (const uint4*)g_wihfh + ((size_t)(dir * 256 + wn0 + 1) * 64) * 32 + lane;
    const uint4* pb1l = (const uint4*)g_wihfl + ((size_t)(dir * 256 + wn0 + 1) * 64) * 32 + lane;

    const uint4* gxh = (const uint4*)g_xfh;
    const uint4* gxl = (const uint4*)g_xfl;

    auto gaddrA = [&](int c, int u) -> size_t {
        int block = u >> 5;
        int ks2 = block >> 3;
        int mtg = block & 7;
        int l4 = u & 31;
        int v = mtile * 2 + (mtg >> 2);
        int t = dir ? (511 - v) : v;
        return ((size_t)(t * 64 + c * 2 + ks2) * 4 + (mtg & 3)) * 32 + l4;
    };

    float acc[4][4][4];
#pragma unroll
    for (int i = 0; i < 4; i++)
#pragma unroll
        for (int n = 0; n < 4; n++)
#pragma unroll
            for (int j = 0; j < 4; j++) acc[i][n][j] = 0.f;

    As[0][tid] = gxh[gaddrA(0, tid)];
    As[0][tid + 256] = gxh[gaddrA(0, tid + 256)];
    Al[0][tid] = gxl[gaddrA(0, tid)];
    Al[0][tid + 256] = gxl[gaddrA(0, tid + 256)];
    __syncthreads();

    uint4 cb0h = pb0h[0], cb0l = pb0l[0], cb1h = pb1h[0], cb1l = pb1l[0];

    for (int c = 0; c < 32; c++) {
        const int cur = c & 1;
        uint4 rh0, rh1, rl0, rl1;
        if (c < 31) {
            rh0 = gxh[gaddrA(c + 1, tid)];
            rh1 = gxh[gaddrA(c + 1, tid + 256)];
            rl0 = gxl[gaddrA(c + 1, tid)];
            rl1 = gxl[gaddrA(c + 1, tid + 256)];
        }
#pragma unroll
        for (int ks2 = 0; ks2 < 2; ks2++) {
            const int kstep = c * 2 + ks2;
            uint4 nb0h = cb0h, nb0l = cb0l, nb1h = cb1h, nb1l = cb1l;
            if (kstep < 63) {
                size_t o = (size_t)(kstep + 1) * 32;
                nb0h = pb0h[o]; nb0l = pb0l[o];
                nb1h = pb1h[o]; nb1l = pb1l[o];
            }
            uint4 ah[4], al[4];
#pragma unroll
            for (int i = 0; i < 4; i++) {
                int sb = (ks2 * 8 + wm * 4 + i) * 32 + lane;
                ah[i] = As[cur][sb];
                al[i] = Al[cur][sb];
            }
#pragma unroll
            for (int i = 0; i < 4; i++) {
                mma16816(acc[i][0], ah[i], cb0h.x, cb0h.y);
                mma16816(acc[i][0], al[i], cb0h.x, cb0h.y);
                mma16816(acc[i][0], ah[i], cb0l.x, cb0l.y);
                mma16816(acc[i][1], ah[i], cb0h.z, cb0h.w);
                mma16816(acc[i][1], al[i], cb0h.z, cb0h.w);
                mma16816(acc[i][1], ah[i], cb0l.z, cb0l.w);
                mma16816(acc[i][2], ah[i], cb1h.x, cb1h.y);
                mma16816(acc[i][2], al[i], cb1h.x, cb1h.y);
                mma16816(acc[i][2], ah[i], cb1l.x, cb1l.y);
                mma16816(acc[i][3], ah[i], cb1h.z, cb1h.w);
                mma16816(acc[i][3], al[i], cb1h.z, cb1h.w);
                mma16816(acc[i][3], ah[i], cb1l.z, cb1l.w);
            }
            cb0h = nb0h; cb0l = nb0l; cb1h = nb1h; cb1l = nb1l;
        }
        if (c < 31) {
            const int nxt = cur ^ 1;
            As[nxt][tid] = rh0; As[nxt][tid + 256] = rh1;
            Al[nxt][tid] = rl0; Al[nxt][tid + 256] = rl1;
            __syncthreads();
        }
    }

    const int r0 = lane >> 2;
    const int cp = (lane & 3) * 2;
    float* outbase = g_gih + (size_t)dir * (Tz * Bz) * Gz;
#pragma unroll
    for (int i = 0; i < 4; i++) {
        const int mtg = wm * 4 + i;
        const int rbase = mtile * 128 + (mtg >> 2) * 64 + (mtg & 3) * 16;
#pragma unroll
        for (int n8 = 0; n8 < 4; n8++) {
            const int col = ntile * 128 + wn4 * 32 + n8 * 8 + cp;
            float2 bv = *(const float2*)(bias + col);
            float* d0 = outbase + (size_t)(rbase + r0) * Gz + col;
            float* d1 = outbase + (size_t)(rbase + r0 + 8) * Gz + col;
            *(float2*)d0 = make_float2(acc[i][n8][0] + bv.x, acc[i][n8][1] + bv.y);
            *(float2*)d1 = make_float2(acc[i][n8][2] + bv.x, acc[i][n8][3] + bv.y);
        }
    }
}

// ---------------- LN stats only: per-row mu, rsigma (no normalize pass) ----------------
__global__ void ln_stats_kernel() {
    const int row = blockIdx.x;
    const float* p = g_gih + (size_t)row * Gz;
    const int tid = threadIdx.x;

    float sum = 0.f, sq = 0.f;
#pragma unroll
    for (int g = 0; g < 4; g++) {
        float4 v = *(const float4*)(p + g * 1024 + tid * 4);
        sum += v.x + v.y + v.z + v.w;
        sq  += v.x * v.x + v.y * v.y + v.z * v.z + v.w * v.w;
    }
    __shared__ float red[512];
    red[tid] = sum; red[256 + tid] = sq;
    __syncthreads();
    for (int s = 128; s > 0; s >>= 1) {
        if (tid < s) { red[tid] += red[tid + s]; red[256 + tid] += red[256 + tid + s]; }
        __syncthreads();
    }
    if (tid == 0) {
        float mu = red[0] * (1.f / Gz);
        float var = red[256] * (1.f / Gz) - mu * mu;
        *(float2*)(g_lnst + (size_t)row * 2) = make_float2(mu, rsqrtf(var + EPSz));
    }
}

// h A-fragment write: element (b=row, k) of dir -> word index
__device__ __forceinline__ void hfrag_addr(int dir, int b, int k, size_t& widx) {
    int kstep = k >> 4;
    int pk = (k >> 1) & 7;
    int r16 = b & 15;
    int mt = b >> 4;
    int T = (r16 & 7) * 4 + (pk & 3);
    int q = (pk >= 4 ? 2 : 0) + (r16 >= 8 ? 1 : 0);
    widx = ((size_t)(dir * 64 + kstep) * 4 + mt) * 128 + T * 4 + q;
}

// ---------------- persistent recurrence: R10 structure + fused ih-LN in phase B ----------------
#define SMEM_BYTES (131072 + 256)

__global__ __launch_bounds__(512, 1)
void lstm_persistent(const float* __restrict__ bhh_f, const float* __restrict__ ghh_f,
                     const float* __restrict__ behh_f,
                     const float* __restrict__ bhh_b, const float* __restrict__ ghh_b,
                     const float* __restrict__ behh_b,
                     const float* __restrict__ gih_f, const float* __restrict__ beih_f,
                     const float* __restrict__ gih_b, const float* __restrict__ beih_b,
                     const float* __restrict__ fwd_init, const float* __restrict__ bwd_init,
                     float* __restrict__ out) {
    extern __shared__ __align__(16) char smem[];
    uint4* ws = (uint4*)smem;                       // [16 wn][16 kstep][32 uint4] W-hi
    float* red = (float*)(smem + 131072);           // [64]

    const int tid = threadIdx.x;
    const int bid = blockIdx.x;
    const int wrp = tid >> 5;
    const int lane = tid & 31;

    // ---- init h0/c0 ----
    for (int i = bid * 512 + tid; i < 2 * Bz * Hz; i += NCTA * 512) {
        int dir0 = i >> 16;
        int b = (i >> 10) & 63;
        int k = i & 1023;
        const float* init = dir0 ? bwd_init : fwd_init;
        float hv = init[k];
        g_c[(size_t)(dir0 * Bz + b) * Hz + k] = init[Hz + k];
        __nv_bfloat16 hh, hl;
        split_bf16(hv, hh, hl);
        size_t widx;
        hfrag_addr(dir0, b, k, widx);
        int half = k & 1;
        ((__nv_bfloat16*)&g_hfh[widx])[half] = hh;
        ((__nv_bfloat16*)&g_hfl[widx])[half] = hl;
    }

    // ---- phase A identifiers: bid = dir*64 + nt*4 + ks ----
    const int dirA = bid >> 6;
    const int nt   = (bid & 63) >> 2;
    const int ks   = bid & 3;
    const int wn   = nt * 16 + wrp;
    const uint4* pbl = (const uint4*)g_wfl + ((size_t)(dirA * 256 + wn) * 64 + ks * 16) * 32 + lane;
    const uint4* pah = (const uint4*)g_hfh + (size_t)(dirA * 64 + ks * 16) * 128 + lane;
    const uint4* pal = (const uint4*)g_hfl + (size_t)(dirA * 64 + ks * 16) * 128 + lane;

    // ---- load per-CTA W-hi slice into SMEM (once) ----
    {
        const uint4* src = (const uint4*)g_wfh
            + ((size_t)(dirA * 256 + nt * 16) * 64 + ks * 16) * 32;
#pragma unroll
        for (int j = 0; j < 16; j++) {
            int u = tid + j * 512;
            int w = u >> 9;
            int rem = u & 511;
            ws[u] = src[(size_t)w * (64 * 32) + rem];
        }
    }

    // ---- phase B identifiers ----
    const int dirB = bid >> 6;
    const int cb   = bid & 63;
    const float* __restrict__ bhh  = dirB ? bhh_b  : bhh_f;
    const float* __restrict__ ghh  = dirB ? ghh_b  : ghh_f;
    const float* __restrict__ behh = dirB ? behh_b : behh_f;
    const float* __restrict__ gihg = dirB ? gih_b  : gih_f;
    const float* __restrict__ gibe = dirB ? beih_b : beih_f;
    float* cptr = g_c + ((size_t)dirB * Bz + cb) * Hz + tid * 2;
    float* o2   = out + (size_t)Bz * Tz * 2 * Hz + (size_t)cb * (2 * Hz) + dirB * Hz + tid * 2;
    const int kstepB = tid >> 3;
    const int pkB = tid & 7;
    const int r16B = cb & 15;
    const int mtB = cb >> 4;
    const size_t hwordB = ((size_t)(dirB * 64 + kstepB) * 4 + mtB) * 128
                          + ((r16B & 7) * 4 + (pkB & 3)) * 4
                          + (pkB >= 4 ? 2 : 0) + (r16B >= 8 ? 1 : 0);

    gbar();   // init + SMEM W visible/loaded

    for (int t = 0; t < Tz; t++) {
        // ---- prefetch this step's raw gih slice + LN stats ----
        float2 gi[4];
        float2 lst;
        {
            const float* gih = g_gih + ((size_t)dirB * Tz * Bz + (size_t)t * Bz + cb) * Gz;
#pragma unroll
            for (int g = 0; g < 4; g++)
                gi[g] = *(const float2*)(gih + g * 1024 + tid * 2);
            lst = *(const float2*)(g_lnst + ((size_t)dirB * Tz * Bz + (size_t)t * Bz + cb) * 2);
        }

        // ================= phase A: HMMA GEMM (16 ksteps) =================
        float acc[4][2][4];
#pragma unroll
        for (int m = 0; m < 4; m++)
#pragma unroll
            for (int n = 0; n < 2; n++)
#pragma unroll
                for (int j = 0; j < 4; j++) acc[m][n][j] = 0.f;

        uint4 cbl = pbl[0];
#pragma unroll 4
        for (int kk = 0; kk < 16; kk++) {
            const uint4* ah4 = pah + (size_t)kk * 128;
            const uint4* al4 = pal + (size_t)kk * 128;
            uint4 ah0 = ah4[0],  ah1 = ah4[32],  ah2 = ah4[64],  ah3 = ah4[96];
            uint4 al0 = al4[0],  al1 = al4[32],  al2 = al4[64],  al3 = al4[96];
            uint4 cbh = ws[(wrp * 16 + kk) * 32 + lane];
            uint4 nbl = cbl;
            if (kk < 15) nbl = pbl[(size_t)(kk + 1) * 32];
            mma16816(acc[0][0], ah0, cbh.x, cbh.y);
            mma16816(acc[0][0], al0, cbh.x, cbh.y);
            mma16816(acc[0][0], ah0, cbl.x, cbl.y);
            mma16816(acc[0][1], ah0, cbh.z, cbh.w);
            mma16816(acc[0][1], al0, cbh.z, cbh.w);
            mma16816(acc[0][1], ah0, cbl.z, cbl.w);
            mma16816(acc[1][0], ah1, cbh.x, cbh.y);
            mma16816(acc[1][0], al1, cbh.x, cbh.y);
            mma16816(acc[1][0], ah1, cbl.x, cbl.y);
            mma16816(acc[1][1], ah1, cbh.z, cbh.w);
            mma16816(acc[1][1], al1, cbh.z, cbh.w);
            mma16816(acc[1][1], ah1, cbl.z, cbl.w);
            mma16816(acc[2][0], ah2, cbh.x, cbh.y);
            mma16816(acc[2][0], al2, cbh.x, cbh.y);
            mma16816(acc[2][0], ah2, cbl.x, cbl.y);
            mma16816(acc[2][1], ah2, cbh.z, cbh.w);
            mma16816(acc[2][1], al2, cbh.z, cbh.w);
            mma16816(acc[2][1], ah2, cbl.z, cbl.w);
            mma16816(acc[3][0], ah3, cbh.x, cbh.y);
            mma16816(acc[3][0], al3, cbh.x, cbh.y);
            mma16816(acc[3][0], ah3, cbl.x, cbl.y);
            mma16816(acc[3][1], ah3, cbh.z, cbh.w);
            mma16816(acc[3][1], al3, cbh.z, cbh.w);
            mma16816(acc[3][1], ah3, cbl.z, cbl.w);
            cbl = nbl;
        }

        // epilogue: write C fragments to g_part [ks][dir][b][col]
        {
            const int r0 = lane >> 2;
            const int cc = wn * 16 + (lane & 3) * 2;
            float* pb = g_part + (size_t)(ks * 2 + dirA) * Bz * Gz;
#pragma unroll
            for (int m = 0; m < 4; m++) {
#pragma unroll
                for (int n = 0; n < 2; n++) {
                    int col = cc + n * 8;
                    *(float2*)&pb[(size_t)(m * 16 + r0) * Gz + col] =
                        make_float2(acc[m][n][0], acc[m][n][1]);
                    *(float2*)&pb[(size_t)(m * 16 + r0 + 8) * Gz + col] =
                        make_float2(acc[m][n][2], acc[m][n][3]);
                }
            }
        }

        gbar();   // all partial tiles visible

        // ================= phase B: sum 4 partials + both LNs + cell =================
        {
            float2 raw[4];
            float sum = 0.f, sq = 0.f;
#pragma unroll
            for (int g = 0; g < 4; g++) {
                int c = g * 1024 + tid * 2;
                const float* pbase = g_part + ((size_t)dirB * Bz + cb) * Gz + c;
                float2 p0 = *(const float2*)(pbase + (size_t)0 * 2 * Bz * Gz);
                float2 p1 = *(const float2*)(pbase + (size_t)1 * 2 * Bz * Gz);
                float2 p2 = *(const float2*)(pbase + (size_t)2 * 2 * Bz * Gz);
                float2 p3 = *(const float2*)(pbase + (size_t)3 * 2 * Bz * Gz);
                float2 bh = *(const float2*)(bhh + c);
                float2 r;
                r.x = p0.x + p1.x + p2.x + p3.x + bh.x;
                r.y = p0.y + p1.y + p2.y + p3.y + bh.y;
                raw[g] = r;
                sum += r.x + r.y;
                sq  += r.x * r.x + r.y * r.y;
            }
#pragma unroll
            for (int off = 16; off; off >>= 1) {
                sum += __shfl_xor_sync(0xffffffffu, sum, off);
                sq  += __shfl_xor_sync(0xffffffffu, sq, off);
            }
            if (lane == 0) { red[wrp] = sum; red[32 + wrp] = sq; }
            __syncthreads();
            float ts = 0.f, tq = 0.f;
#pragma unroll
            for (int i = 0; i < 16; i++) { ts += red[i]; tq += red[32 + i]; }
            float mu = ts * (1.f / Gz);
            float var = tq * (1.f / Gz) - mu * mu;
            float sc = rsqrtf(var + EPSz);

            const float mi = lst.x;       // ih-LN mean
            const float si = lst.y;       // ih-LN rsigma
            float gate[4][2];
#pragma unroll
            for (int g = 0; g < 4; g++) {
                int c = g * 1024 + tid * 2;
                float2 gg  = *(const float2*)(ghh + c);
                float2 be  = *(const float2*)(behh + c);
                float2 gig = *(const float2*)(gihg + c);
                float2 gib = *(const float2*)(gibe + c);
                gate[g][0] = (gi[g].x - mi) * si * gig.x + gib.x
                           + (raw[g].x - mu) * sc * gg.x + be.x;
                gate[g][1] = (gi[g].y - mi) * si * gig.y + gib.y
                           + (raw[g].y - mu) * sc * gg.y + be.y;
            }
            float* optr = out + ((size_t)cb * Tz + t) * (2 * Hz) + dirB * Hz + tid * 2;
            float hn2[2];
#pragma unroll
            for (int q = 0; q < 2; q++) {
                float iv = sig_ap(gate[0][q]);
                float fv = sig_ap(gate[1][q]);
                float gv = tanh_ap(gate[2][q]);
                float ov = sig_ap(gate[3][q]);
                float cn = fv * cptr[q] + iv * gv;
                float hn = ov * tanh_ap(cn);
                cptr[q] = cn;
                hn2[q] = hn;
                optr[q] = hn;
                if (t == Tz - 1) o2[q] = hn;
            }
            __nv_bfloat16 h0, l0, h1, l1;
            split_bf16(hn2[0], h0, l0);
            split_bf16(hn2[1], h1, l1);
            g_hfh[hwordB] = pack2(h0, h1);
            g_hfl[hwordB] = pack2(l0, l1);
        }

        gbar();   // new h visible
    }
}

// ---------------- launch ----------------
extern "C" void kernel_launch(void* const* d_in, const int* in_sizes, int n_in,
                              void* d_out, int out_size) {
    const float* x      = (const float*)d_in[0];
    const float* wih_f  = (const float*)d_in[1];
    const float* whh_f  = (const float*)d_in[2];
    const float* bih_f  = (const float*)d_in[3];
    const float* bhh_f  = (const float*)d_in[4];
    const float* gih_f  = (const float*)d_in[5];
    const float* beih_f = (const float*)d_in[6];
    const float* ghh_f  = (const float*)d_in[7];
    const float* behh_f = (const float*)d_in[8];
    const float* wih_b  = (const float*)d_in[9];
    const float* whh_b  = (const float*)d_in[10];
    const float* bih_b  = (const float*)d_in[11];
    const float* bhh_b  = (const float*)d_in[12];
    const float* gih_b  = (const float*)d_in[13];
    const float* beih_b = (const float*)d_in[14];
    const float* ghh_b  = (const float*)d_in[15];
    const float* behh_b = (const float*)d_in[16];
    const float* fwd_init = (const float*)d_in[17];
    const float* bwd_init = (const float*)d_in[18];
    float* out = (float*)d_out;

    static int smem_set = 0;
    if (!smem_set) {
        cudaFuncSetAttribute(lstm_persistent,
                             cudaFuncAttributeMaxDynamicSharedMemorySize, SMEM_BYTES);
        smem_set = 1;
    }

    prep_wfrag_kernel<<<4096, 256>>>(whh_f, whh_b, 0);
    prep_wfrag_kernel<<<4096, 256>>>(wih_f, wih_b, 1);
    prep_x_kernel<<<65536, 256>>>(x);
    gemm_ih_hmma<<<dim3(64, 256), 256>>>(bih_f, bih_b);
    ln_stats_kernel<<<65536, 256>>>();
    lstm_persistent<<<NCTA, 512, SMEM_BYTES>>>(bhh_f, ghh_f, behh_f,
                                               bhh_b, ghh_b, behh_b,
                                               gih_f, beih_f, gih_b, beih_b,
                                               fwd_init, bwd_init, out);
}

// round 14
// speedup vs baseline: 1.0878x; 1.0043x over previous
#include <cuda_runtime.h>
#include <cuda_bf16.h>
#include <math.h>
#include <stdint.h>

#define Bz 64
#define Tz 512
#define Dz 1024
#define Hz 1024
#define Gz 4096          // 4*H
#define EPSz 1e-5f
#define NCTA 128

typedef unsigned long long ull;

// ---------------- scratch (device globals; no runtime allocation) ----------------
__device__ float g_gih[(size_t)2 * Tz * Bz * Gz];      // RAW input gates + bias [dir][t][b][4H]
__device__ float g_lnst[(size_t)2 * Tz * Bz * 2];      // per-row LN stats: mu, rsigma
__device__ __align__(16) unsigned g_wfh[(size_t)2 * 256 * 64 * 128];
__device__ __align__(16) unsigned g_wfl[(size_t)2 * 256 * 64 * 128];
__device__ __align__(16) unsigned g_wihfh[(size_t)2 * 256 * 64 * 128];
__device__ __align__(16) unsigned g_wihfl[(size_t)2 * 256 * 64 * 128];
__device__ __align__(16) unsigned g_xfh[(size_t)512 * 64 * 4 * 128];
__device__ __align__(16) unsigned g_xfl[(size_t)512 * 64 * 4 * 128];
__device__ __align__(16) unsigned g_hfh[2 * 64 * 4 * 128];
__device__ __align__(16) unsigned g_hfl[2 * 64 * 4 * 128];
__device__ float g_part[8 * Bz * Gz];                  // [ks 0..3][dir][b][4H]
__device__ float g_c[2 * Bz * Hz];                     // cell state
// per-dir barrier state (128B-spaced to avoid sector sharing)
__device__ unsigned g_cnt2[2 * 32];
__device__ unsigned g_gen2[2 * 32];

// ---------------- helpers ----------------
__device__ __forceinline__ void split_bf16(float v, __nv_bfloat16& hi, __nv_bfloat16& lo) {
    hi = __float2bfloat16(v);
    lo = __float2bfloat16(v - __bfloat162float(hi));
}
__device__ __forceinline__ unsigned pack2(__nv_bfloat16 a, __nv_bfloat16 b) {
    return (unsigned)__bfloat16_as_ushort(a) | ((unsigned)__bfloat16_as_ushort(b) << 16);
}
__device__ __forceinline__ float tanh_ap(float x) {
    float y;
    asm("tanh.approx.f32 %0, %1;" : "=f"(y) : "f"(x));
    return y;
}
__device__ __forceinline__ float sig_ap(float x) {
    return 0.5f * tanh_ap(0.5f * x) + 0.5f;
}

// HMMA m16n8k16 bf16 row.col, f32 accumulate
__device__ __forceinline__ void mma16816(float* c, const uint4& a, unsigned b0, unsigned b1) {
    asm volatile(
        "mma.sync.aligned.m16n8k16.row.col.f32.bf16.bf16.f32 "
        "{%0,%1,%2,%3}, {%4,%5,%6,%7}, {%8,%9}, {%0,%1,%2,%3};"
        : "+f"(c[0]), "+f"(c[1]), "+f"(c[2]), "+f"(c[3])
        : "r"(a.x), "r"(a.y), "r"(a.z), "r"(a.w), "r"(b0), "r"(b1));
}

// per-dir sense-reversing atomic barrier (proven R10 mechanism, 64 arrivals).
__device__ __forceinline__ void gbar_d(int dgrp) {
    __syncthreads();
    if (threadIdx.x == 0) {
        unsigned* cnt = &g_cnt2[dgrp * 32];
        unsigned* gen = &g_gen2[dgrp * 32];
        unsigned g = *(volatile unsigned*)gen;
        __threadfence();
        unsigned old = atomicAdd(cnt, 1u);
        if (old == 63) {
            atomicExch(cnt, 0u);
            __threadfence();
            atomicAdd(gen, 1u);
        } else {
            while (*(volatile unsigned*)gen == g) __nanosleep(32);
        }
        __threadfence();
    }
    __syncthreads();
}

// ---------------- prep: weight [4096][1024] -> bf16 hi/lo B-fragment images ----------------
__global__ void prep_wfrag_kernel(const float* __restrict__ w_f, const float* __restrict__ w_b,
                                  int sel) {
    unsigned* __restrict__ outh = sel ? g_wihfh : g_wfh;
    unsigned* __restrict__ outl = sel ? g_wihfl : g_wfl;
    int gid = blockIdx.x * 256 + threadIdx.x;
    int T     = gid & 31;
    int kstep = (gid >> 5) & 63;
    int wn    = (gid >> 11) & 255;
    int dir   = gid >> 19;
    const float* __restrict__ W = dir ? w_b : w_f;
    unsigned hw[4], lw[4];
#pragma unroll
    for (int q = 0; q < 4; q++) {
        int c = wn * 16 + (q >> 1) * 8 + (T >> 2);
        int k = kstep * 16 + ((q & 1) * 4 + (T & 3)) * 2;
        float2 v = *(const float2*)(W + (size_t)c * Hz + k);
        __nv_bfloat16 h0, l0, h1, l1;
        split_bf16(v.x, h0, l0);
        split_bf16(v.y, h1, l1);
        hw[q] = pack2(h0, h1);
        lw[q] = pack2(l0, l1);
    }
    size_t base = ((size_t)(dir * 256 + wn) * 64 + kstep) * 128 + T * 4;
    *(uint4*)&outh[base] = make_uint4(hw[0], hw[1], hw[2], hw[3]);
    *(uint4*)&outl[base] = make_uint4(lw[0], lw[1], lw[2], lw[3]);
}

// ---------------- prep: x -> bf16 hi/lo A-fragment images ----------------
__global__ void prep_x_kernel(const float* __restrict__ x) {
    int gid = blockIdx.x * 256 + threadIdx.x;
    int kw = gid & 511;
    int b  = (gid >> 9) & 63;
    int t  = gid >> 15;
    float2 v = *(const float2*)(x + ((size_t)b * Tz + t) * Dz + kw * 2);
    __nv_bfloat16 h0, l0, h1, l1;
    split_bf16(v.x, h0, l0);
    split_bf16(v.y, h1, l1);
    int kstep = kw >> 3;
    int pk = kw & 7;
    int r16 = b & 15;
    int mt = b >> 4;
    int T = (r16 & 7) * 4 + (pk & 3);
    int q = (pk >= 4 ? 2 : 0) + (r16 >= 8 ? 1 : 0);
    size_t widx = ((size_t)(t * 64 + kstep) * 4 + mt) * 128 + T * 4 + q;
    g_xfh[widx] = pack2(h0, h1);
    g_xfl[widx] = pack2(l0, l1);
}

// ---------------- input-side GEMM: HMMA bf16-split (unchanged) ----------------
__global__ __launch_bounds__(256)
void gemm_ih_hmma(const float* __restrict__ bias_f, const float* __restrict__ bias_b) {
    __shared__ uint4 As[2][512];
    __shared__ uint4 Al[2][512];
    const int tid = threadIdx.x;
    const int lane = tid & 31;
    const int wrp = tid >> 5;
    const int dir = blockIdx.x >> 5;
    const int ntile = blockIdx.x & 31;
    const int mtile = blockIdx.y;
    const int wm = wrp >> 2;
    const int wn4 = wrp & 3;
    const float* __restrict__ bias = dir ? bias_b : bias_f;

    const int wn0 = ntile * 8 + wn4 * 2;
    const uint4* pb0h = (const uint4*)g_wihfh + ((size_t)(dir * 256 + wn0) * 64) * 32 + lane;
    const uint4* pb0l = (const uint4*)g_wihfl + ((size_t)(dir * 256 + wn0) * 64) * 32 + lane;
    const uint4* pb1h = (const uint4*)g_wihfh + ((size_t)(dir * 256 + wn0 + 1) * 64) * 32 + lane;
    const uint4* pb1l = (const uint4*)g_wihfl + ((size_t)(dir * 256 + wn0 + 1) * 64) * 32 + lane;

    const uint4* gxh = (const uint4*)g_xfh;
    const uint4* gxl = (const uint4*)g_xfl;

    auto gaddrA = [&](int c, int u) -> size_t {
        int block = u >> 5;
        int ks2 = block >> 3;
        int mtg = block & 7;
        int l4 = u & 31;
        int v = mtile * 2 + (mtg >> 2);
        int t = dir ? (511 - v) : v;
        return ((size_t)(t * 64 + c * 2 + ks2) * 4 + (mtg & 3)) * 32 + l4;
    };

    float acc[4][4][4];
#pragma unroll
    for (int i = 0; i < 4; i++)
#pragma unroll
        for (int n = 0; n < 4; n++)
#pragma unroll
            for (int j = 0; j < 4; j++) acc[i][n][j] = 0.f;

    As[0][tid] = gxh[gaddrA(0, tid)];
    As[0][tid + 256] = gxh[gaddrA(0, tid + 256)];
    Al[0][tid] = gxl[gaddrA(0, tid)];
    Al[0][tid + 256] = gxl[gaddrA(0, tid + 256)];
    __syncthreads();

    uint4 cb0h = pb0h[0], cb0l = pb0l[0], cb1h = pb1h[0], cb1l = pb1l[0];

    for (int c = 0; c < 32; c++) {
        const int cur = c & 1;
        uint4 rh0, rh1, rl0, rl1;
        if (c < 31) {
            rh0 = gxh[gaddrA(c + 1, tid)];
            rh1 = gxh[gaddrA(c + 1, tid + 256)];
            rl0 = gxl[gaddrA(c + 1, tid)];
            rl1 = gxl[gaddrA(c + 1, tid + 256)];
        }
#pragma unroll
        for (int ks2 = 0; ks2 < 2; ks2++) {
            const int kstep = c * 2 + ks2;
            uint4 nb0h = cb0h, nb0l = cb0l, nb1h = cb1h, nb1l = cb1l;
            if (kstep < 63) {
                size_t o = (size_t)(kstep + 1) * 32;
                nb0h = pb0h[o]; nb0l = pb0l[o];
                nb1h = pb1h[o]; nb1l = pb1l[o];
            }
            uint4 ah[4], al[4];
#pragma unroll
            for (int i = 0; i < 4; i++) {
                int sb = (ks2 * 8 + wm * 4 + i) * 32 + lane;
                ah[i] = As[cur][sb];
                al[i] = Al[cur][sb];
            }
#pragma unroll
            for (int i = 0; i < 4; i++) {
                mma16816(acc[i][0], ah[i], cb0h.x, cb0h.y);
                mma16816(acc[i][0], al[i], cb0h.x, cb0h.y);
                mma16816(acc[i][0], ah[i], cb0l.x, cb0l.y);
                mma16816(acc[i][1], ah[i], cb0h.z, cb0h.w);
                mma16816(acc[i][1], al[i], cb0h.z, cb0h.w);
                mma16816(acc[i][1], ah[i], cb0l.z, cb0l.w);
                mma16816(acc[i][2], ah[i], cb1h.x, cb1h.y);
                mma16816(acc[i][2], al[i], cb1h.x, cb1h.y);
                mma16816(acc[i][2], ah[i], cb1l.x, cb1l.y);
                mma16816(acc[i][3], ah[i], cb1h.z, cb1h.w);
                mma16816(acc[i][3], al[i], cb1h.z, cb1h.w);
                mma16816(acc[i][3], ah[i], cb1l.z, cb1l.w);
            }
            cb0h = nb0h; cb0l = nb0l; cb1h = nb1h; cb1l = nb1l;
        }
        if (c < 31) {
            const int nxt = cur ^ 1;
            As[nxt][tid] = rh0; As[nxt][tid + 256] = rh1;
            Al[nxt][tid] = rl0; Al[nxt][tid + 256] = rl1;
            __syncthreads();
        }
    }

    const int r0 = lane >> 2;
    const int cp = (lane & 3) * 2;
    float* outbase = g_gih + (size_t)dir * (Tz * Bz) * Gz;
#pragma unroll
    for (int i = 0; i < 4; i++) {
        const int mtg = wm * 4 + i;
        const int rbase = mtile * 128 + (mtg >> 2) * 64 + (mtg & 3) * 16;
#pragma unroll
        for (int n8 = 0; n8 < 4; n8++) {
            const int col = ntile * 128 + wn4 * 32 + n8 * 8 + cp;
            float2 bv = *(const float2*)(bias + col);
            float* d0 = outbase + (size_t)(rbase + r0) * Gz + col;
            float* d1 = outbase + (size_t)(rbase + r0 + 8) * Gz + col;
            *(float2*)d0 = make_float2(acc[i][n8][0] + bv.x, acc[i][n8][1] + bv.y);
            *(float2*)d1 = make_float2(acc[i][n8][2] + bv.x, acc[i][n8][3] + bv.y);
        }
    }
}

// ---------------- LN stats only: per-row mu, rsigma ----------------
__global__ void ln_stats_kernel() {
    const int row = blockIdx.x;
    const float* p = g_gih + (size_t)row * Gz;
    const int tid = threadIdx.x;

    float sum = 0.f, sq = 0.f;
#pragma unroll
    for (int g = 0; g < 4; g++) {
        float4 v = *(const float4*)(p + g * 1024 + tid * 4);
        sum += v.x + v.y + v.z + v.w;
        sq  += v.x * v.x + v.y * v.y + v.z * v.z + v.w * v.w;
    }
    __shared__ float red[512];
    red[tid] = sum; red[256 + tid] = sq;
    __syncthreads();
    for (int s = 128; s > 0; s >>= 1) {
        if (tid < s) { red[tid] += red[tid + s]; red[256 + tid] += red[256 + tid + s]; }
        __syncthreads();
    }
    if (tid == 0) {
        float mu = red[0] * (1.f / Gz);
        float var = red[256] * (1.f / Gz) - mu * mu;
        *(float2*)(g_lnst + (size_t)row * 2) = make_float2(mu, rsqrtf(var + EPSz));
    }
}

// h A-fragment write: element (b=row, k) of dir -> word index
__device__ __forceinline__ void hfrag_addr(int dir, int b, int k, size_t& widx) {
    int kstep = k >> 4;
    int pk = (k >> 1) & 7;
    int r16 = b & 15;
    int mt = b >> 4;
    int T = (r16 & 7) * 4 + (pk & 3);
    int q = (pk >= 4 ? 2 : 0) + (r16 >= 8 ? 1 : 0);
    widx = ((size_t)(dir * 64 + kstep) * 4 + mt) * 128 + T * 4 + q;
}

// ---------------- persistent recurrence: R13 + per-dir atomic barriers ----------------
#define SMEM_BYTES (131072 + 256)

__global__ __launch_bounds__(512, 1)
void lstm_persistent(const float* __restrict__ bhh_f, const float* __restrict__ ghh_f,
                     const float* __restrict__ behh_f,
                     const float* __restrict__ bhh_b, const float* __restrict__ ghh_b,
                     const float* __restrict__ behh_b,
                     const float* __restrict__ gih_f, const float* __restrict__ beih_f,
                     const float* __restrict__ gih_b, const float* __restrict__ beih_b,
                     const float* __restrict__ fwd_init, const float* __restrict__ bwd_init,
                     float* __restrict__ out) {
    extern __shared__ __align__(16) char smem[];
    uint4* ws = (uint4*)smem;                       // [16 wn][16 kstep][32 uint4] W-hi
    float* red = (float*)(smem + 131072);           // [64]

    const int tid = threadIdx.x;
    const int bid = blockIdx.x;
    const int wrp = tid >> 5;
    const int lane = tid & 31;
    const int dgrp = bid >> 6;
    const int sub  = bid & 63;

    // ---- init h0/c0 (per-dir partition; fwd/bwd state disjoint) ----
    for (int e = sub * 512 + tid; e < Bz * Hz; e += 64 * 512) {
        int b = e >> 10;
        int k = e & 1023;
        const float* init = dgrp ? bwd_init : fwd_init;
        float hv = init[k];
        g_c[(size_t)(dgrp * Bz + b) * Hz + k] = init[Hz + k];
        __nv_bfloat16 hh, hl;
        split_bf16(hv, hh, hl);
        size_t widx;
        hfrag_addr(dgrp, b, k, widx);
        int half = k & 1;
        ((__nv_bfloat16*)&g_hfh[widx])[half] = hh;
        ((__nv_bfloat16*)&g_hfl[widx])[half] = hl;
    }

    // ---- phase A identifiers: bid = dir*64 + nt*4 + ks ----
    const int dirA = dgrp;
    const int nt   = sub >> 2;
    const int ks   = sub & 3;
    const int wn   = nt * 16 + wrp;
    const uint4* pbl = (const uint4*)g_wfl + ((size_t)(dirA * 256 + wn) * 64 + ks * 16) * 32 + lane;
    const uint4* pah = (const uint4*)g_hfh + (size_t)(dirA * 64 + ks * 16) * 128 + lane;
    const uint4* pal = (const uint4*)g_hfl + (size_t)(dirA * 64 + ks * 16) * 128 + lane;

    // ---- load per-CTA W-hi slice into SMEM (once) ----
    {
        const uint4* src = (const uint4*)g_wfh
            + ((size_t)(dirA * 256 + nt * 16) * 64 + ks * 16) * 32;
#pragma unroll
        for (int j = 0; j < 16; j++) {
            int u = tid + j * 512;
            int w = u >> 9;
            int rem = u & 511;
            ws[u] = src[(size_t)w * (64 * 32) + rem];
        }
    }

    // ---- phase B identifiers ----
    const int dirB = dgrp;
    const int cb   = sub;
    const float* __restrict__ bhh  = dirB ? bhh_b  : bhh_f;
    const float* __restrict__ ghh  = dirB ? ghh_b  : ghh_f;
    const float* __restrict__ behh = dirB ? behh_b : behh_f;
    const float* __restrict__ gihg = dirB ? gih_b  : gih_f;
    const float* __restrict__ gibe = dirB ? beih_b : beih_f;
    float* cptr = g_c + ((size_t)dirB * Bz + cb) * Hz + tid * 2;
    float* o2   = out + (size_t)Bz * Tz * 2 * Hz + (size_t)cb * (2 * Hz) + dirB * Hz + tid * 2;
    const int kstepB = tid >> 3;
    const int pkB = tid & 7;
    const int r16B = cb & 15;
    const int mtB = cb >> 4;
    const size_t hwordB = ((size_t)(dirB * 64 + kstepB) * 4 + mtB) * 128
                          + ((r16B & 7) * 4 + (pkB & 3)) * 4
                          + (pkB >= 4 ? 2 : 0) + (r16B >= 8 ? 1 : 0);

    gbar_d(dgrp);   // init + SMEM W visible/loaded (per dir; state is dir-disjoint)

    for (int t = 0; t < Tz; t++) {
        // ---- prefetch this step's raw gih slice + LN stats ----
        float2 gi[4];
        float2 lst;
        {
            const float* gih = g_gih + ((size_t)dirB * Tz * Bz + (size_t)t * Bz + cb) * Gz;
#pragma unroll
            for (int g = 0; g < 4; g++)
                gi[g] = *(const float2*)(gih + g * 1024 + tid * 2);
            lst = *(const float2*)(g_lnst + ((size_t)dirB * Tz * Bz + (size_t)t * Bz + cb) * 2);
        }

        // ================= phase A: HMMA GEMM (16 ksteps) =================
        float acc[4][2][4];
#pragma unroll
        for (int m = 0; m < 4; m++)
#pragma unroll
            for (int n = 0; n < 2; n++)
#pragma unroll
                for (int j = 0; j < 4; j++) acc[m][n][j] = 0.f;

        uint4 cbl = pbl[0];
#pragma unroll 4
        for (int kk = 0; kk < 16; kk++) {
            const uint4* ah4 = pah + (size_t)kk * 128;
            const uint4* al4 = pal + (size_t)kk * 128;
            uint4 ah0 = ah4[0],  ah1 = ah4[32],  ah2 = ah4[64],  ah3 = ah4[96];
            uint4 al0 = al4[0],  al1 = al4[32],  al2 = al4[64],  al3 = al4[96];
            uint4 cbh = ws[(wrp * 16 + kk) * 32 + lane];
            uint4 nbl = cbl;
            if (kk < 15) nbl = pbl[(size_t)(kk + 1) * 32];
            mma16816(acc[0][0], ah0, cbh.x, cbh.y);
            mma16816(acc[0][0], al0, cbh.x, cbh.y);
            mma16816(acc[0][0], ah0, cbl.x, cbl.y);
            mma16816(acc[0][1], ah0, cbh.z, cbh.w);
            mma16816(acc[0][1], al0, cbh.z, cbh.w);
            mma16816(acc[0][1], ah0, cbl.z, cbl.w);
            mma16816(acc[1][0], ah1, cbh.x, cbh.y);
            mma16816(acc[1][0], al1, cbh.x, cbh.y);
            mma16816(acc[1][0], ah1, cbl.x, cbl.y);
            mma16816(acc[1][1], ah1, cbh.z, cbh.w);
            mma16816(acc[1][1], al1, cbh.z, cbh.w);
            mma16816(acc[1][1], ah1, cbl.z, cbl.w);
            mma16816(acc[2][0], ah2, cbh.x, cbh.y);
            mma16816(acc[2][0], al2, cbh.x, cbh.y);
            mma16816(acc[2][0], ah2, cbl.x, cbl.y);
            mma16816(acc[2][1], ah2, cbh.z, cbh.w);
            mma16816(acc[2][1], al2, cbh.z, cbh.w);
            mma16816(acc[2][1], ah2, cbl.z, cbl.w);
            mma16816(acc[3][0], ah3, cbh.x, cbh.y);
            mma16816(acc[3][0], al3, cbh.x, cbh.y);
            mma16816(acc[3][0], ah3, cbl.x, cbl.y);
            mma16816(acc[3][1], ah3, cbh.z, cbh.w);
            mma16816(acc[3][1], al3, cbh.z, cbh.w);
            mma16816(acc[3][1], ah3, cbl.z, cbl.w);
            cbl = nbl;
        }

        // epilogue: write C fragments to g_part [ks][dir][b][col]
        {
            const int r0 = lane >> 2;
            const int cc = wn * 16 + (lane & 3) * 2;
            float* pb = g_part + (size_t)(ks * 2 + dirA) * Bz * Gz;
#pragma unroll
            for (int m = 0; m < 4; m++) {
#pragma unroll
                for (int n = 0; n < 2; n++) {
                    int col = cc + n * 8;
                    *(float2*)&pb[(size_t)(m * 16 + r0) * Gz + col] =
                        make_float2(acc[m][n][0], acc[m][n][1]);
                    *(float2*)&pb[(size_t)(m * 16 + r0 + 8) * Gz + col] =
                        make_float2(acc[m][n][2], acc[m][n][3]);
                }
            }
        }

        gbar_d(dgrp);   // this dir's partial tiles visible

        // ================= phase B: sum 4 partials + both LNs + cell =================
        {
            float2 raw[4];
            float sum = 0.f, sq = 0.f;
#pragma unroll
            for (int g = 0; g < 4; g++) {
                int c = g * 1024 + tid * 2;
                const float* pbase = g_part + ((size_t)dirB * Bz + cb) * Gz + c;
                float2 p0 = *(const float2*)(pbase + (size_t)0 * 2 * Bz * Gz);
                float2 p1 = *(const float2*)(pbase + (size_t)1 * 2 * Bz * Gz);
                float2 p2 = *(const float2*)(pbase + (size_t)2 * 2 * Bz * Gz);
                float2 p3 = *(const float2*)(pbase + (size_t)3 * 2 * Bz * Gz);
                float2 bh = *(const float2*)(bhh + c);
                float2 r;
                r.x = p0.x + p1.x + p2.x + p3.x + bh.x;
                r.y = p0.y + p1.y + p2.y + p3.y + bh.y;
                raw[g] = r;
                sum += r.x + r.y;
                sq  += r.x * r.x + r.y * r.y;
            }
#pragma unroll
            for (int off = 16; off; off >>= 1) {
                sum += __shfl_xor_sync(0xffffffffu, sum, off);
                sq  += __shfl_xor_sync(0xffffffffu, sq, off);
            }
            if (lane == 0) { red[wrp] = sum; red[32 + wrp] = sq; }
            __syncthreads();
            float ts = 0.f, tq = 0.f;
#pragma unroll
            for (int i = 0; i < 16; i++) { ts += red[i]; tq += red[32 + i]; }
            float mu = ts * (1.f / Gz);
            float var = tq * (1.f / Gz) - mu * mu;
            float sc = rsqrtf(var + EPSz);

            const float mi = lst.x;
            const float si = lst.y;
            float gate[4][2];
#pragma unroll
            for (int g = 0; g < 4; g++) {
                int c = g * 1024 + tid * 2;
                float2 gg  = *(const float2*)(ghh + c);
                float2 be  = *(const float2*)(behh + c);
                float2 gig = *(const float2*)(gihg + c);
                float2 gib = *(const float2*)(gibe + c);
                gate[g][0] = (gi[g].x - mi) * si * gig.x + gib.x
                           + (raw[g].x - mu) * sc * gg.x + be.x;
                gate[g][1] = (gi[g].y - mi) * si * gig.y + gib.y
                           + (raw[g].y - mu) * sc * gg.y + be.y;
            }
            float* optr = out + ((size_t)cb * Tz + t) * (2 * Hz) + dirB * Hz + tid * 2;
            float hn2[2];
#pragma unroll
            for (int q = 0; q < 2; q++) {
                float iv = sig_ap(gate[0][q]);
                float fv = sig_ap(gate[1][q]);
                float gv = tanh_ap(gate[2][q]);
                float ov = sig_ap(gate[3][q]);
                float cn = fv * cptr[q] + iv * gv;
                float hn = ov * tanh_ap(cn);
                cptr[q] = cn;
                hn2[q] = hn;
                optr[q] = hn;
                if (t == Tz - 1) o2[q] = hn;
            }
            __nv_bfloat16 h0, l0, h1, l1;
            split_bf16(hn2[0], h0, l0);
            split_bf16(hn2[1], h1, l1);
            g_hfh[hwordB] = pack2(h0, h1);
            g_hfl[hwordB] = pack2(l0, l1);
        }

        gbar_d(dgrp);   // this dir's new h visible
    }
}

// ---------------- launch ----------------
extern "C" void kernel_launch(void* const* d_in, const int* in_sizes, int n_in,
                              void* d_out, int out_size) {
    const float* x      = (const float*)d_in[0];
    const float* wih_f  = (const float*)d_in[1];
    const float* whh_f  = (const float*)d_in[2];
    const float* bih_f  = (const float*)d_in[3];
    const float* bhh_f  = (const float*)d_in[4];
    const float* gih_f  = (const float*)d_in[5];
    const float* beih_f = (const float*)d_in[6];
    const float* ghh_f  = (const float*)d_in[7];
    const float* behh_f = (const float*)d_in[8];
    const float* wih_b  = (const float*)d_in[9];
    const float* whh_b  = (const float*)d_in[10];
    const float* bih_b  = (const float*)d_in[11];
    const float* bhh_b  = (const float*)d_in[12];
    const float* gih_b  = (const float*)d_in[13];
    const float* beih_b = (const float*)d_in[14];
    const float* ghh_b  = (const float*)d_in[15];
    const float* behh_b = (const float*)d_in[16];
    const float* fwd_init = (const float*)d_in[17];
    const float* bwd_init = (const float*)d_in[18];
    float* out = (float*)d_out;

    static int smem_set = 0;
    if (!smem_set) {
        cudaFuncSetAttribute(lstm_persistent,
                             cudaFuncAttributeMaxDynamicSharedMemorySize, SMEM_BYTES);
        smem_set = 1;
    }

    prep_wfrag_kernel<<<4096, 256>>>(whh_f, whh_b, 0);
    prep_wfrag_kernel<<<4096, 256>>>(wih_f, wih_b, 1);
    prep_x_kernel<<<65536, 256>>>(x);
    gemm_ih_hmma<<<dim3(64, 256), 256>>>(bih_f, bih_b);
    ln_stats_kernel<<<65536, 256>>>();
    lstm_persistent<<<NCTA, 512, SMEM_BYTES>>>(bhh_f, ghh_f, behh_f,
                                               bhh_b, ghh_b, behh_b,
                                               gih_f, beih_f, gih_b, beih_b,
                                               fwd_init, bwd_init, out);
}

// round 15
// speedup vs baseline: 1.1459x; 1.0534x over previous
#include <cuda_runtime.h>
#include <cuda_bf16.h>
#include <math.h>
#include <stdint.h>

#define Bz 64
#define Tz 512
#define Dz 1024
#define Hz 1024
#define Gz 4096          // 4*H
#define EPSz 1e-5f
#define NCTA 128

typedef unsigned long long ull;

// ---------------- scratch (device globals; no runtime allocation) ----------------
__device__ float g_gih[(size_t)2 * Tz * Bz * Gz];      // RAW input gates + bias [dir][t][b][4H]
__device__ float g_lnst[(size_t)2 * Tz * Bz * 2];      // per-row LN stats: mu, rsigma
__device__ __align__(16) unsigned g_wfh[(size_t)2 * 256 * 64 * 128];
__device__ __align__(16) unsigned g_wfl[(size_t)2 * 256 * 64 * 128];
__device__ __align__(16) unsigned g_wihfh[(size_t)2 * 256 * 64 * 128];
__device__ __align__(16) unsigned g_wihfl[(size_t)2 * 256 * 64 * 128];
__device__ __align__(16) unsigned g_xfh[(size_t)512 * 64 * 4 * 128];
__device__ __align__(16) unsigned g_xfl[(size_t)512 * 64 * 4 * 128];
__device__ __align__(16) unsigned g_hfh[2 * 64 * 4 * 128];
__device__ __align__(16) unsigned g_hfl[2 * 64 * 4 * 128];
__device__ float g_part[8 * Bz * Gz];                  // [ks 0..3][dir][b][4H]
__device__ float g_c[2 * Bz * Hz];                     // cell state
// per-dir barrier state (128B-spaced)
__device__ unsigned g_cnt2[2 * 32];
__device__ unsigned g_gen2[2 * 32];

// ---------------- helpers ----------------
__device__ __forceinline__ void split_bf16(float v, __nv_bfloat16& hi, __nv_bfloat16& lo) {
    hi = __float2bfloat16(v);
    lo = __float2bfloat16(v - __bfloat162float(hi));
}
__device__ __forceinline__ unsigned pack2(__nv_bfloat16 a, __nv_bfloat16 b) {
    return (unsigned)__bfloat16_as_ushort(a) | ((unsigned)__bfloat16_as_ushort(b) << 16);
}
__device__ __forceinline__ float tanh_ap(float x) {
    float y;
    asm("tanh.approx.f32 %0, %1;" : "=f"(y) : "f"(x));
    return y;
}
__device__ __forceinline__ float sig_ap(float x) {
    return 0.5f * tanh_ap(0.5f * x) + 0.5f;
}
__device__ __forceinline__ uint32_t smem_u32(const void* p) {
    uint32_t a;
    asm("{ .reg .u64 t; cvta.to.shared.u64 t, %1; cvt.u32.u64 %0, t; }" : "=r"(a) : "l"(p));
    return a;
}
#define CP16(dst, src) \
    asm volatile("cp.async.cg.shared.global [%0], [%1], 16;" :: "r"(dst), "l"(src) : "memory")
#define CP_COMMIT() asm volatile("cp.async.commit_group;" ::: "memory")
#define CP_WAIT1()  asm volatile("cp.async.wait_group 1;" ::: "memory")
#define CP_WAIT0()  asm volatile("cp.async.wait_group 0;" ::: "memory")

// HMMA m16n8k16 bf16 row.col, f32 accumulate
__device__ __forceinline__ void mma16816(float* c, const uint4& a, unsigned b0, unsigned b1) {
    asm volatile(
        "mma.sync.aligned.m16n8k16.row.col.f32.bf16.bf16.f32 "
        "{%0,%1,%2,%3}, {%4,%5,%6,%7}, {%8,%9}, {%0,%1,%2,%3};"
        : "+f"(c[0]), "+f"(c[1]), "+f"(c[2]), "+f"(c[3])
        : "r"(a.x), "r"(a.y), "r"(a.z), "r"(a.w), "r"(b0), "r"(b1));
}

// per-dir sense-reversing atomic barrier (proven R10 mechanism, 64 arrivals).
__device__ __forceinline__ void gbar_d(int dgrp) {
    __syncthreads();
    if (threadIdx.x == 0) {
        unsigned* cnt = &g_cnt2[dgrp * 32];
        unsigned* gen = &g_gen2[dgrp * 32];
        unsigned g = *(volatile unsigned*)gen;
        __threadfence();
        unsigned old = atomicAdd(cnt, 1u);
        if (old == 63) {
            atomicExch(cnt, 0u);
            __threadfence();
            atomicAdd(gen, 1u);
        } else {
            while (*(volatile unsigned*)gen == g) __nanosleep(32);
        }
        __threadfence();
    }
    __syncthreads();
}

// ---------------- prep: weight [4096][1024] -> bf16 hi/lo B-fragment images ----------------
__global__ void prep_wfrag_kernel(const float* __restrict__ w_f, const float* __restrict__ w_b,
                                  int sel) {
    unsigned* __restrict__ outh = sel ? g_wihfh : g_wfh;
    unsigned* __restrict__ outl = sel ? g_wihfl : g_wfl;
    int gid = blockIdx.x * 256 + threadIdx.x;
    int T     = gid & 31;
    int kstep = (gid >> 5) & 63;
    int wn    = (gid >> 11) & 255;
    int dir   = gid >> 19;
    const float* __restrict__ W = dir ? w_b : w_f;
    unsigned hw[4], lw[4];
#pragma unroll
    for (int q = 0; q < 4; q++) {
        int c = wn * 16 + (q >> 1) * 8 + (T >> 2);
        int k = kstep * 16 + ((q & 1) * 4 + (T & 3)) * 2;
        float2 v = *(const float2*)(W + (size_t)c * Hz + k);
        __nv_bfloat16 h0, l0, h1, l1;
        split_bf16(v.x, h0, l0);
        split_bf16(v.y, h1, l1);
        hw[q] = pack2(h0, h1);
        lw[q] = pack2(l0, l1);
    }
    size_t base = ((size_t)(dir * 256 + wn) * 64 + kstep) * 128 + T * 4;
    *(uint4*)&outh[base] = make_uint4(hw[0], hw[1], hw[2], hw[3]);
    *(uint4*)&outl[base] = make_uint4(lw[0], lw[1], lw[2], lw[3]);
}

// ---------------- prep: x -> bf16 hi/lo A-fragment images ----------------
__global__ void prep_x_kernel(const float* __restrict__ x) {
    int gid = blockIdx.x * 256 + threadIdx.x;
    int kw = gid & 511;
    int b  = (gid >> 9) & 63;
    int t  = gid >> 15;
    float2 v = *(const float2*)(x + ((size_t)b * Tz + t) * Dz + kw * 2);
    __nv_bfloat16 h0, l0, h1, l1;
    split_bf16(v.x, h0, l0);
    split_bf16(v.y, h1, l1);
    int kstep = kw >> 3;
    int pk = kw & 7;
    int r16 = b & 15;
    int mt = b >> 4;
    int T = (r16 & 7) * 4 + (pk & 3);
    int q = (pk >= 4 ? 2 : 0) + (r16 >= 8 ? 1 : 0);
    size_t widx = ((size_t)(t * 64 + kstep) * 4 + mt) * 128 + T * 4 + q;
    g_xfh[widx] = pack2(h0, h1);
    g_xfl[widx] = pack2(l0, l1);
}

// ---------------- input-side GEMM: HMMA bf16-split (unchanged) ----------------
__global__ __launch_bounds__(256)
void gemm_ih_hmma(const float* __restrict__ bias_f, const float* __restrict__ bias_b) {
    __shared__ uint4 As[2][512];
    __shared__ uint4 Al[2][512];
    const int tid = threadIdx.x;
    const int lane = tid & 31;
    const int wrp = tid >> 5;
    const int dir = blockIdx.x >> 5;
    const int ntile = blockIdx.x & 31;
    const int mtile = blockIdx.y;
    const int wm = wrp >> 2;
    const int wn4 = wrp & 3;
    const float* __restrict__ bias = dir ? bias_b : bias_f;

    const int wn0 = ntile * 8 + wn4 * 2;
    const uint4* pb0h = (const uint4*)g_wihfh + ((size_t)(dir * 256 + wn0) * 64) * 32 + lane;
    const uint4* pb0l = (const uint4*)g_wihfl + ((size_t)(dir * 256 + wn0) * 64) * 32 + lane;
    const uint4* pb1h = (const uint4*)g_wihfh + ((size_t)(dir * 256 + wn0 + 1) * 64) * 32 + lane;
    const uint4* pb1l = (const uint4*)g_wihfl + ((size_t)(dir * 256 + wn0 + 1) * 64) * 32 + lane;

    const uint4* gxh = (const uint4*)g_xfh;
    const uint4* gxl = (const uint4*)g_xfl;

    auto gaddrA = [&](int c, int u) -> size_t {
        int block = u >> 5;
        int ks2 = block >> 3;
        int mtg = block & 7;
        int l4 = u & 31;
        int v = mtile * 2 + (mtg >> 2);
        int t = dir ? (511 - v) : v;
        return ((size_t)(t * 64 + c * 2 + ks2) * 4 + (mtg & 3)) * 32 + l4;
    };

    float acc[4][4][4];
#pragma unroll
    for (int i = 0; i < 4; i++)
#pragma unroll
        for (int n = 0; n < 4; n++)
#pragma unroll
            for (int j = 0; j < 4; j++) acc[i][n][j] = 0.f;

    As[0][tid] = gxh[gaddrA(0, tid)];
    As[0][tid + 256] = gxh[gaddrA(0, tid + 256)];
    Al[0][tid] = gxl[gaddrA(0, tid)];
    Al[0][tid + 256] = gxl[gaddrA(0, tid + 256)];
    __syncthreads();

    uint4 cb0h = pb0h[0], cb0l = pb0l[0], cb1h = pb1h[0], cb1l = pb1l[0];

    for (int c = 0; c < 32; c++) {
        const int cur = c & 1;
        uint4 rh0, rh1, rl0, rl1;
        if (c < 31) {
            rh0 = gxh[gaddrA(c + 1, tid)];
            rh1 = gxh[gaddrA(c + 1, tid + 256)];
            rl0 = gxl[gaddrA(c + 1, tid)];
            rl1 = gxl[gaddrA(c + 1, tid + 256)];
        }
#pragma unroll
        for (int ks2 = 0; ks2 < 2; ks2++) {
            const int kstep = c * 2 + ks2;
            uint4 nb0h = cb0h, nb0l = cb0l, nb1h = cb1h, nb1l = cb1l;
            if (kstep < 63) {
                size_t o = (size_t)(kstep + 1) * 32;
                nb0h = pb0h[o]; nb0l = pb0l[o];
                nb1h = pb1h[o]; nb1l = pb1l[o];
            }
            uint4 ah[4], al[4];
#pragma unroll
            for (int i = 0; i < 4; i++) {
                int sb = (ks2 * 8 + wm * 4 + i) * 32 + lane;
                ah[i] = As[cur][sb];
                al[i] = Al[cur][sb];
            }
#pragma unroll
            for (int i = 0; i < 4; i++) {
                mma16816(acc[i][0], ah[i], cb0h.x, cb0h.y);
                mma16816(acc[i][0], al[i], cb0h.x, cb0h.y);
                mma16816(acc[i][0], ah[i], cb0l.x, cb0l.y);
                mma16816(acc[i][1], ah[i], cb0h.z, cb0h.w);
                mma16816(acc[i][1], al[i], cb0h.z, cb0h.w);
                mma16816(acc[i][1], ah[i], cb0l.z, cb0l.w);
                mma16816(acc[i][2], ah[i], cb1h.x, cb1h.y);
                mma16816(acc[i][2], al[i], cb1h.x, cb1h.y);
                mma16816(acc[i][2], ah[i], cb1l.x, cb1l.y);
                mma16816(acc[i][3], ah[i], cb1h.z, cb1h.w);
                mma16816(acc[i][3], al[i], cb1h.z, cb1h.w);
                mma16816(acc[i][3], ah[i], cb1l.z, cb1l.w);
            }
            cb0h = nb0h; cb0l = nb0l; cb1h = nb1h; cb1l = nb1l;
        }
        if (c < 31) {
            const int nxt = cur ^ 1;
            As[nxt][tid] = rh0; As[nxt][tid + 256] = rh1;
            Al[nxt][tid] = rl0; Al[nxt][tid + 256] = rl1;
            __syncthreads();
        }
    }

    const int r0 = lane >> 2;
    const int cp = (lane & 3) * 2;
    float* outbase = g_gih + (size_t)dir * (Tz * Bz) * Gz;
#pragma unroll
    for (int i = 0; i < 4; i++) {
        const int mtg = wm * 4 + i;
        const int rbase = mtile * 128 + (mtg >> 2) * 64 + (mtg & 3) * 16;
#pragma unroll
        for (int n8 = 0; n8 < 4; n8++) {
            const int col = ntile * 128 + wn4 * 32 + n8 * 8 + cp;
            float2 bv = *(const float2*)(bias + col);
            float* d0 = outbase + (size_t)(rbase + r0) * Gz + col;
            float* d1 = outbase + (size_t)(rbase + r0 + 8) * Gz + col;
            *(float2*)d0 = make_float2(acc[i][n8][0] + bv.x, acc[i][n8][1] + bv.y);
            *(float2*)d1 = make_float2(acc[i][n8][2] + bv.x, acc[i][n8][3] + bv.y);
        }
    }
}

// ---------------- LN stats only: per-row mu, rsigma ----------------
__global__ void ln_stats_kernel() {
    const int row = blockIdx.x;
    const float* p = g_gih + (size_t)row * Gz;
    const int tid = threadIdx.x;

    float sum = 0.f, sq = 0.f;
#pragma unroll
    for (int g = 0; g < 4; g++) {
        float4 v = *(const float4*)(p + g * 1024 + tid * 4);
        sum += v.x + v.y + v.z + v.w;
        sq  += v.x * v.x + v.y * v.y + v.z * v.z + v.w * v.w;
    }
    __shared__ float red[512];
    red[tid] = sum; red[256 + tid] = sq;
    __syncthreads();
    for (int s = 128; s > 0; s >>= 1) {
        if (tid < s) { red[tid] += red[tid + s]; red[256 + tid] += red[256 + tid + s]; }
        __syncthreads();
    }
    if (tid == 0) {
        float mu = red[0] * (1.f / Gz);
        float var = red[256] * (1.f / Gz) - mu * mu;
        *(float2*)(g_lnst + (size_t)row * 2) = make_float2(mu, rsqrtf(var + EPSz));
    }
}

// h A-fragment write: element (b=row, k) of dir -> word index
__device__ __forceinline__ void hfrag_addr(int dir, int b, int k, size_t& widx) {
    int kstep = k >> 4;
    int pk = (k >> 1) & 7;
    int r16 = b & 15;
    int mt = b >> 4;
    int T = (r16 & 7) * 4 + (pk & 3);
    int q = (pk >= 4 ? 2 : 0) + (r16 >= 8 ? 1 : 0);
    widx = ((size_t)(dir * 64 + kstep) * 4 + mt) * 128 + T * 4 + q;
}

// ---------------- persistent recurrence: R14 + cp.async h-slice staging ----------------
// SMEM: ws 131072 (W-hi) | hsh 32768 | hsl 32768 | red 256
#define SM_HSH 131072
#define SM_HSL 163840
#define SM_RED 196608
#define SMEM_BYTES (196608 + 256)

__global__ __launch_bounds__(512, 1)
void lstm_persistent(const float* __restrict__ bhh_f, const float* __restrict__ ghh_f,
                     const float* __restrict__ behh_f,
                     const float* __restrict__ bhh_b, const float* __restrict__ ghh_b,
                     const float* __restrict__ behh_b,
                     const float* __restrict__ gih_f, const float* __restrict__ beih_f,
                     const float* __restrict__ gih_b, const float* __restrict__ beih_b,
                     const float* __restrict__ fwd_init, const float* __restrict__ bwd_init,
                     float* __restrict__ out) {
    extern __shared__ __align__(16) char smem[];
    uint4* ws  = (uint4*)smem;                       // [16 wn][16 kstep][32 uint4] W-hi
    uint4* hsh = (uint4*)(smem + SM_HSH);            // h-hi slice [16 kk][128 uint4]
    uint4* hsl = (uint4*)(smem + SM_HSL);            // h-lo slice
    float* red = (float*)(smem + SM_RED);

    const int tid = threadIdx.x;
    const int bid = blockIdx.x;
    const int wrp = tid >> 5;
    const int lane = tid & 31;
    const int dgrp = bid >> 6;
    const int sub  = bid & 63;

    // ---- init h0/c0 (per-dir partition) ----
    for (int e = sub * 512 + tid; e < Bz * Hz; e += 64 * 512) {
        int b = e >> 10;
        int k = e & 1023;
        const float* init = dgrp ? bwd_init : fwd_init;
        float hv = init[k];
        g_c[(size_t)(dgrp * Bz + b) * Hz + k] = init[Hz + k];
        __nv_bfloat16 hh, hl;
        split_bf16(hv, hh, hl);
        size_t widx;
        hfrag_addr(dgrp, b, k, widx);
        int half = k & 1;
        ((__nv_bfloat16*)&g_hfh[widx])[half] = hh;
        ((__nv_bfloat16*)&g_hfl[widx])[half] = hl;
    }

    // ---- phase A identifiers: bid = dir*64 + nt*4 + ks ----
    const int dirA = dgrp;
    const int nt   = sub >> 2;
    const int ks   = sub & 3;
    const int wn   = nt * 16 + wrp;
    const uint4* pbl = (const uint4*)g_wfl + ((size_t)(dirA * 256 + wn) * 64 + ks * 16) * 32 + lane;

    // h-slice (contiguous 32KB hi + 32KB lo) global base for this (dir, ks)
    const char* srcH = (const char*)((const uint4*)g_hfh + (size_t)(dirA * 64 + ks * 16) * 128);
    const char* srcL = (const char*)((const uint4*)g_hfl + (size_t)(dirA * 64 + ks * 16) * 128);
    const uint32_t hsh_s = smem_u32(smem) + SM_HSH;
    const uint32_t hsl_s = smem_u32(smem) + SM_HSL;
    const uint32_t toff = tid * 16;

    // ---- load per-CTA W-hi slice into SMEM (once) ----
    {
        const uint4* src = (const uint4*)g_wfh
            + ((size_t)(dirA * 256 + nt * 16) * 64 + ks * 16) * 32;
#pragma unroll
        for (int j = 0; j < 16; j++) {
            int u = tid + j * 512;
            int w = u >> 9;
            int rem = u & 511;
            ws[u] = src[(size_t)w * (64 * 32) + rem];
        }
    }

    // ---- phase B identifiers ----
    const int dirB = dgrp;
    const int cb   = sub;
    const float* __restrict__ bhh  = dirB ? bhh_b  : bhh_f;
    const float* __restrict__ ghh  = dirB ? ghh_b  : ghh_f;
    const float* __restrict__ behh = dirB ? behh_b : behh_f;
    const float* __restrict__ gihg = dirB ? gih_b  : gih_f;
    const float* __restrict__ gibe = dirB ? beih_b : beih_f;
    float* cptr = g_c + ((size_t)dirB * Bz + cb) * Hz + tid * 2;
    float* o2   = out + (size_t)Bz * Tz * 2 * Hz + (size_t)cb * (2 * Hz) + dirB * Hz + tid * 2;
    const int kstepB = tid >> 3;
    const int pkB = tid & 7;
    const int r16B = cb & 15;
    const int mtB = cb >> 4;
    const size_t hwordB = ((size_t)(dirB * 64 + kstepB) * 4 + mtB) * 128
                          + ((r16B & 7) * 4 + (pkB & 3)) * 4
                          + (pkB >= 4 ? 2 : 0) + (r16B >= 8 ? 1 : 0);

    gbar_d(dgrp);   // init + SMEM W visible/loaded

    for (int t = 0; t < Tz; t++) {
        // ---- stage h slice into SMEM via cp.async (2 commit groups of 8 kk each) ----
        CP16(hsh_s + toff,         srcH + toff);
        CP16(hsh_s + toff + 8192,  srcH + toff + 8192);
        CP16(hsl_s + toff,         srcL + toff);
        CP16(hsl_s + toff + 8192,  srcL + toff + 8192);
        CP_COMMIT();
        CP16(hsh_s + toff + 16384, srcH + toff + 16384);
        CP16(hsh_s + toff + 24576, srcH + toff + 24576);
        CP16(hsl_s + toff + 16384, srcL + toff + 16384);
        CP16(hsl_s + toff + 24576, srcL + toff + 24576);
        CP_COMMIT();

        // ---- prefetch this step's raw gih slice + LN stats (overlaps cp.async) ----
        float2 gi[4];
        float2 lst;
        {
            const float* gih = g_gih + ((size_t)dirB * Tz * Bz + (size_t)t * Bz + cb) * Gz;
#pragma unroll
            for (int g = 0; g < 4; g++)
                gi[g] = *(const float2*)(gih + g * 1024 + tid * 2);
            lst = *(const float2*)(g_lnst + ((size_t)dirB * Tz * Bz + (size_t)t * Bz + cb) * 2);
        }

        // ================= phase A: HMMA GEMM (16 ksteps, A from SMEM) =================
        float acc[4][2][4];
#pragma unroll
        for (int m = 0; m < 4; m++)
#pragma unroll
            for (int n = 0; n < 2; n++)
#pragma unroll
                for (int j = 0; j < 4; j++) acc[m][n][j] = 0.f;

        uint4 cbl = pbl[0];

        CP_WAIT1();
        __syncthreads();
#pragma unroll
        for (int kk = 0; kk < 8; kk++) {
            const uint4* ah4 = hsh + kk * 128 + lane;
            const uint4* al4 = hsl + kk * 128 + lane;
            uint4 ah0 = ah4[0],  ah1 = ah4[32],  ah2 = ah4[64],  ah3 = ah4[96];
            uint4 al0 = al4[0],  al1 = al4[32],  al2 = al4[64],  al3 = al4[96];
            uint4 cbh = ws[(wrp * 16 + kk) * 32 + lane];
            uint4 nbl = pbl[(size_t)(kk + 1) * 32];
            mma16816(acc[0][0], ah0, cbh.x, cbh.y);
            mma16816(acc[0][0], al0, cbh.x, cbh.y);
            mma16816(acc[0][0], ah0, cbl.x, cbl.y);
            mma16816(acc[0][1], ah0, cbh.z, cbh.w);
            mma16816(acc[0][1], al0, cbh.z, cbh.w);
            mma16816(acc[0][1], ah0, cbl.z, cbl.w);
            mma16816(acc[1][0], ah1, cbh.x, cbh.y);
            mma16816(acc[1][0], al1, cbh.x, cbh.y);
            mma16816(acc[1][0], ah1, cbl.x, cbl.y);
            mma16816(acc[1][1], ah1, cbh.z, cbh.w);
            mma16816(acc[1][1], al1, cbh.z, cbh.w);
            mma16816(acc[1][1], ah1, cbl.z, cbl.w);
            mma16816(acc[2][0], ah2, cbh.x, cbh.y);
            mma16816(acc[2][0], al2, cbh.x, cbh.y);
            mma16816(acc[2][0], ah2, cbl.x, cbl.y);
            mma16816(acc[2][1], ah2, cbh.z, cbh.w);
            mma16816(acc[2][1], al2, cbh.z, cbh.w);
            mma16816(acc[2][1], ah2, cbl.z, cbl.w);
            mma16816(acc[3][0], ah3, cbh.x, cbh.y);
            mma16816(acc[3][0], al3, cbh.x, cbh.y);
            mma16816(acc[3][0], ah3, cbl.x, cbl.y);
            mma16816(acc[3][1], ah3, cbh.z, cbh.w);
            mma16816(acc[3][1], al3, cbh.z, cbh.w);
            mma16816(acc[3][1], ah3, cbl.z, cbl.w);
            cbl = nbl;
        }
        CP_WAIT0();
        __syncthreads();
#pragma unroll
        for (int kk = 8; kk < 16; kk++) {
            const uint4* ah4 = hsh + kk * 128 + lane;
            const uint4* al4 = hsl + kk * 128 + lane;
            uint4 ah0 = ah4[0],  ah1 = ah4[32],  ah2 = ah4[64],  ah3 = ah4[96];
            uint4 al0 = al4[0],  al1 = al4[32],  al2 = al4[64],  al3 = al4[96];
            uint4 cbh = ws[(wrp * 16 + kk) * 32 + lane];
            uint4 nbl = cbl;
            if (kk < 15) nbl = pbl[(size_t)(kk + 1) * 32];
            mma16816(acc[0][0], ah0, cbh.x, cbh.y);
            mma16816(acc[0][0], al0, cbh.x, cbh.y);
            mma16816(acc[0][0], ah0, cbl.x, cbl.y);
            mma16816(acc[0][1], ah0, cbh.z, cbh.w);
            mma16816(acc[0][1], al0, cbh.z, cbh.w);
            mma16816(acc[0][1], ah0, cbl.z, cbl.w);
            mma16816(acc[1][0], ah1, cbh.x, cbh.y);
            mma16816(acc[1][0], al1, cbh.x, cbh.y);
            mma16816(acc[1][0], ah1, cbl.x, cbl.y);
            mma16816(acc[1][1], ah1, cbh.z, cbh.w);
            mma16816(acc[1][1], al1, cbh.z, cbh.w);
            mma16816(acc[1][1], ah1, cbl.z, cbl.w);
            mma16816(acc[2][0], ah2, cbh.x, cbh.y);
            mma16816(acc[2][0], al2, cbh.x, cbh.y);
            mma16816(acc[2][0], ah2, cbl.x, cbl.y);
            mma16816(acc[2][1], ah2, cbh.z, cbh.w);
            mma16816(acc[2][1], al2, cbh.z, cbh.w);
            mma16816(acc[2][1], ah2, cbl.z, cbl.w);
            mma16816(acc[3][0], ah3, cbh.x, cbh.y);
            mma16816(acc[3][0], al3, cbh.x, cbh.y);
            mma16816(acc[3][0], ah3, cbl.x, cbl.y);
            mma16816(acc[3][1], ah3, cbh.z, cbh.w);
            mma16816(acc[3][1], al3, cbh.z, cbh.w);
            mma16816(acc[3][1], ah3, cbl.z, cbl.w);
            cbl = nbl;
        }

        // epilogue: write C fragments to g_part [ks][dir][b][col]
        {
            const int r0 = lane >> 2;
            const int cc = wn * 16 + (lane & 3) * 2;
            float* pb = g_part + (size_t)(ks * 2 + dirA) * Bz * Gz;
#pragma unroll
            for (int m = 0; m < 4; m++) {
#pragma unroll
                for (int n = 0; n < 2; n++) {
                    int col = cc + n * 8;
                    *(float2*)&pb[(size_t)(m * 16 + r0) * Gz + col] =
                        make_float2(acc[m][n][0], acc[m][n][1]);
                    *(float2*)&pb[(size_t)(m * 16 + r0 + 8) * Gz + col] =
                        make_float2(acc[m][n][2], acc[m][n][3]);
                }
            }
        }

        gbar_d(dgrp);   // this dir's partial tiles visible

        // ================= phase B: sum 4 partials + both LNs + cell =================
        {
            float2 raw[4];
            float sum = 0.f, sq = 0.f;
#pragma unroll
            for (int g = 0; g < 4; g++) {
                int c = g * 1024 + tid * 2;
                const float* pbase = g_part + ((size_t)dirB * Bz + cb) * Gz + c;
                float2 p0 = *(const float2*)(pbase + (size_t)0 * 2 * Bz * Gz);
                float2 p1 = *(const float2*)(pbase + (size_t)1 * 2 * Bz * Gz);
                float2 p2 = *(const float2*)(pbase + (size_t)2 * 2 * Bz * Gz);
                float2 p3 = *(const float2*)(pbase + (size_t)3 * 2 * Bz * Gz);
                float2 bh = *(const float2*)(bhh + c);
                float2 r;
                r.x = p0.x + p1.x + p2.x + p3.x + bh.x;
                r.y = p0.y + p1.y + p2.y + p3.y + bh.y;
                raw[g] = r;
                sum += r.x + r.y;
                sq  += r.x * r.x + r.y * r.y;
            }
#pragma unroll
            for (int off = 16; off; off >>= 1) {
                sum += __shfl_xor_sync(0xffffffffu, sum, off);
                sq  += __shfl_xor_sync(0xffffffffu, sq, off);
            }
            if (lane == 0) { red[wrp] = sum; red[32 + wrp] = sq; }
            __syncthreads();
            float ts = 0.f, tq = 0.f;
#pragma unroll
            for (int i = 0; i < 16; i++) { ts += red[i]; tq += red[32 + i]; }
            float mu = ts * (1.f / Gz);
            float var = tq * (1.f / Gz) - mu * mu;
            float sc = rsqrtf(var + EPSz);

            const float mi = lst.x;
            const float si = lst.y;
            float gate[4][2];
#pragma unroll
            for (int g = 0; g < 4; g++) {
                int c = g * 1024 + tid * 2;
                float2 gg  = *(const float2*)(ghh + c);
                float2 be  = *(const float2*)(behh + c);
                float2 gig = *(const float2*)(gihg + c);
                float2 gib = *(const float2*)(gibe + c);
                gate[g][0] = (gi[g].x - mi) * si * gig.x + gib.x
                           + (raw[g].x - mu) * sc * gg.x + be.x;
                gate[g][1] = (gi[g].y - mi) * si * gig.y + gib.y
                           + (raw[g].y - mu) * sc * gg.y + be.y;
            }
            float* optr = out + ((size_t)cb * Tz + t) * (2 * Hz) + dirB * Hz + tid * 2;
            float hn2[2];
#pragma unroll
            for (int q = 0; q < 2; q++) {
                float iv = sig_ap(gate[0][q]);
                float fv = sig_ap(gate[1][q]);
                float gv = tanh_ap(gate[2][q]);
                float ov = sig_ap(gate[3][q]);
                float cn = fv * cptr[q] + iv * gv;
                float hn = ov * tanh_ap(cn);
                cptr[q] = cn;
                hn2[q] = hn;
                optr[q] = hn;
                if (t == Tz - 1) o2[q] = hn;
            }
            __nv_bfloat16 h0, l0, h1, l1;
            split_bf16(hn2[0], h0, l0);
            split_bf16(hn2[1], h1, l1);
            g_hfh[hwordB] = pack2(h0, h1);
            g_hfl[hwordB] = pack2(l0, l1);
        }

        gbar_d(dgrp);   // this dir's new h visible
    }
}

// ---------------- launch ----------------
extern "C" void kernel_launch(void* const* d_in, const int* in_sizes, int n_in,
                              void* d_out, int out_size) {
    const float* x      = (const float*)d_in[0];
    const float* wih_f  = (const float*)d_in[1];
    const float* whh_f  = (const float*)d_in[2];
    const float* bih_f  = (const float*)d_in[3];
    const float* bhh_f  = (const float*)d_in[4];
    const float* gih_f  = (const float*)d_in[5];
    const float* beih_f = (const float*)d_in[6];
    const float* ghh_f  = (const float*)d_in[7];
    const float* behh_f = (const float*)d_in[8];
    const float* wih_b  = (const float*)d_in[9];
    const float* whh_b  = (const float*)d_in[10];
    const float* bih_b  = (const float*)d_in[11];
    const float* bhh_b  = (const float*)d_in[12];
    const float* gih_b  = (const float*)d_in[13];
    const float* beih_b = (const float*)d_in[14];
    const float* ghh_b  = (const float*)d_in[15];
    const float* behh_b = (const float*)d_in[16];
    const float* fwd_init = (const float*)d_in[17];
    const float* bwd_init = (const float*)d_in[18];
    float* out = (float*)d_out;

    static int smem_set = 0;
    if (!smem_set) {
        cudaFuncSetAttribute(lstm_persistent,
                             cudaFuncAttributeMaxDynamicSharedMemorySize, SMEM_BYTES);
        smem_set = 1;
    }

    prep_wfrag_kernel<<<4096, 256>>>(whh_f, whh_b, 0);
    prep_wfrag_kernel<<<4096, 256>>>(wih_f, wih_b, 1);
    prep_x_kernel<<<65536, 256>>>(x);
    gemm_ih_hmma<<<dim3(64, 256), 256>>>(bih_f, bih_b);
    ln_stats_kernel<<<65536, 256>>>();
    lstm_persistent<<<NCTA, 512, SMEM_BYTES>>>(bhh_f, ghh_f, behh_f,
                                               bhh_b, ghh_b, behh_b,
                                               gih_f, beih_f, gih_b, beih_b,
                                               fwd_init, bwd_init, out);
}